// round 12
// baseline (speedup 1.0000x reference)
#include <cuda_runtime.h>
#include <cuda_fp16.h>
#include <math.h>
#include <stdint.h>

// ---------------------------------------------------------------------------
// Problem constants
// ---------------------------------------------------------------------------
#define Bsz   8
#define Tseq  1024
#define EMB   768
#define NH    12
#define HD    64
#define NTOK  (Bsz * Tseq)          // 8192
#define FFND  (4 * EMB)             // 3072

// ---------------------------------------------------------------------------
// Scratch (device globals — allocation-free)
// ---------------------------------------------------------------------------
__device__ __half g_h16  [NTOK * EMB];                 // LN output (fp16)
__device__ __half g_qkv16[3L * NTOK * EMB];            // q|k|v, each [B,H,T,D]
__device__ __half g_ctx16[NTOK * EMB];                 // [B,T,E]
__device__ __half g_ffn16[NTOK * FFND];                // gelu(h @ W1^T)
__device__ float  g_x2   [NTOK * EMB];                 // fp32 residual stream
// fp16 weight copies
__device__ __half g_wqkv16[3 * EMB * EMB];             // wq|wk|wv rows
__device__ __half g_wo16[EMB * EMB];
__device__ __half g_w116[FFND * EMB];
__device__ __half g_w216[EMB * FFND];

// ---------------------------------------------------------------------------
// PTX helpers
// ---------------------------------------------------------------------------
__device__ __forceinline__ void cp16s(uint32_t dst, const void* src) {
    asm volatile("cp.async.ca.shared.global [%0], [%1], 16;" :: "r"(dst), "l"(src));
}
__device__ __forceinline__ void cp_commit() {
    asm volatile("cp.async.commit_group;" ::: "memory");
}
template<int N>
__device__ __forceinline__ void cp_wait() {
    asm volatile("cp.async.wait_group %0;" :: "n"(N) : "memory");
}
__device__ __forceinline__ uint32_t sw128(uint32_t o) {   // Swizzle<3,4,3>, 128B rows
    return o ^ ((o >> 3) & 0x70);
}
__device__ __forceinline__ uint32_t h2_u32(__half2 h) {
    return *reinterpret_cast<uint32_t*>(&h);
}
__device__ __forceinline__ void ldsm4(uint32_t* r, uint32_t addr) {
    asm volatile("ldmatrix.sync.aligned.m8n8.x4.shared.b16 {%0,%1,%2,%3}, [%4];"
        : "=r"(r[0]), "=r"(r[1]), "=r"(r[2]), "=r"(r[3]) : "r"(addr));
}
__device__ __forceinline__ void ldsm4t(uint32_t* r, uint32_t addr) {
    asm volatile("ldmatrix.sync.aligned.m8n8.x4.trans.shared.b16 {%0,%1,%2,%3}, [%4];"
        : "=r"(r[0]), "=r"(r[1]), "=r"(r[2]), "=r"(r[3]) : "r"(addr));
}
__device__ __forceinline__ void mma16816(float* d, const uint32_t* a, const uint32_t* b) {
    asm volatile(
        "mma.sync.aligned.m16n8k16.row.col.f32.f16.f16.f32 "
        "{%0,%1,%2,%3}, {%4,%5,%6,%7}, {%8,%9}, {%0,%1,%2,%3};"
        : "+f"(d[0]), "+f"(d[1]), "+f"(d[2]), "+f"(d[3])
        : "r"(a[0]), "r"(a[1]), "r"(a[2]), "r"(a[3]), "r"(b[0]), "r"(b[1]));
}

// ---------------------------------------------------------------------------
// Merged fp32 -> fp16 weight converter. blockIdx.y selects segment.
// ---------------------------------------------------------------------------
__global__ void f2h_all_k(const float* __restrict__ wq, const float* __restrict__ wk,
                          const float* __restrict__ wv, const float* __restrict__ wo,
                          const float* __restrict__ w1, const float* __restrict__ w2,
                          __half* __restrict__ dqkv, __half* __restrict__ dwo,
                          __half* __restrict__ dw1, __half* __restrict__ dw2) {
    const int seg = blockIdx.y;
    const int nblk = (seg < 4) ? (EMB * EMB / 1024) : (FFND * EMB / 1024);
    if (blockIdx.x >= nblk) return;
    const float* s;
    __half* d;
    switch (seg) {
        case 0: s = wq; d = dqkv;                 break;
        case 1: s = wk; d = dqkv + EMB * EMB;     break;
        case 2: s = wv; d = dqkv + 2 * EMB * EMB; break;
        case 3: s = wo; d = dwo;                  break;
        case 4: s = w1; d = dw1;                  break;
        default: s = w2; d = dw2;                 break;
    }
    int i = (blockIdx.x * 256 + threadIdx.x) * 4;
    float4 v = *(const float4*)(s + i);
    *(__half2*)(d + i)     = __floats2half2_rn(v.x, v.y);
    *(__half2*)(d + i + 2) = __floats2half2_rn(v.z, v.w);
}

// ---------------------------------------------------------------------------
// LayerNorm, warp-per-row (no block barriers): fp32 in, fp16 out.
// 256 threads = 8 warps = 8 rows per block; 1024 blocks.
// ---------------------------------------------------------------------------
__global__ void layernorm_k(const float* __restrict__ x, __half* __restrict__ o,
                            const float* __restrict__ sc, const float* __restrict__ sh) {
    const int lane = threadIdx.x & 31;
    const long row = (long)blockIdx.x * 8 + (threadIdx.x >> 5);
    const float4* p = (const float4*)(x + row * EMB);
    const float4* s4 = (const float4*)sc;
    const float4* b4 = (const float4*)sh;
    uint2* q = (uint2*)(o + row * EMB);

    float4 v[6];
    float sum = 0.0f, sq = 0.0f;
    #pragma unroll
    for (int j = 0; j < 6; j++) {
        v[j] = p[lane + 32 * j];
        sum += v[j].x + v[j].y + v[j].z + v[j].w;
        sq  += v[j].x * v[j].x + v[j].y * v[j].y + v[j].z * v[j].z + v[j].w * v[j].w;
    }
    #pragma unroll
    for (int ofs = 16; ofs; ofs >>= 1) {
        sum += __shfl_xor_sync(0xffffffffu, sum, ofs);
        sq  += __shfl_xor_sync(0xffffffffu, sq,  ofs);
    }
    float mean = sum * (1.0f / EMB);
    float var  = sq * (1.0f / EMB) - mean * mean;
    float rstd = rsqrtf(var + 1e-5f);

    #pragma unroll
    for (int j = 0; j < 6; j++) {
        float4 sv = s4[lane + 32 * j];
        float4 bv = b4[lane + 32 * j];
        __half2 h0 = __floats2half2_rn((v[j].x - mean) * rstd * sv.x + bv.x,
                                       (v[j].y - mean) * rstd * sv.y + bv.y);
        __half2 h1 = __floats2half2_rn((v[j].z - mean) * rstd * sv.z + bv.z,
                                       (v[j].w - mean) * rstd * sv.w + bv.w);
        q[lane + 32 * j] = make_uint2(h2_u32(h0), h2_u32(h1));
    }
}

// ---------------------------------------------------------------------------
// Flash attention: fused QK^T -> causal online softmax -> @V.
// 4-slot K/V ring, prefetch distance 2, ONE barrier per tile (slot reuse is
// separated by two top-of-loop barriers). Heavy q-tiles scheduled first.
// ---------------------------------------------------------------------------
__global__ void __launch_bounds__(256, 2)
flash_k(const __half* __restrict__ Qg, const __half* __restrict__ Kg,
        const __half* __restrict__ Vg, __half* __restrict__ O) {
    const int qt  = gridDim.x - 1 - blockIdx.x;     // heavy tiles first
    const int bh  = blockIdx.y;
    const int row0 = qt * 128;
    const int b = bh / NH, hh = bh % NH;

    extern __shared__ char smraw[];
    const uint32_t smQ = (uint32_t)__cvta_generic_to_shared(smraw);   // 16 KB
    const uint32_t smK = smQ + 128 * 128;                             // 4 x 8 KB
    const uint32_t smV = smK + 4 * 64 * 128;                          // 4 x 8 KB

    const int tid = threadIdx.x, lane = tid & 31, w = tid >> 5;
    const int g = lane >> 2, tig = lane & 3;
    const int aRow = (lane & 7) + ((lane >> 3) & 1) * 8, aChk = lane >> 4;
    const int bRow = (lane & 7) + (lane >> 4) * 8,       bChk = (lane >> 3) & 1;

    const __half* Qb = Qg + ((long)bh << 10) * HD;
    const __half* Kb = Kg + ((long)bh << 10) * HD;
    const __half* Vb = Vg + ((long)bh << 10) * HD;

    for (int i = tid; i < 128 * 8; i += 256) {
        int r = i >> 3, c = i & 7;
        cp16s(smQ + sw128(r * 128 + c * 16), Qb + (long)(row0 + r) * HD + c * 8);
    }
    cp_commit();

    const int nkv = 2 * qt + 2;
    auto load_kv = [&](int it, int s) {
        int kv0 = it * 64;
        #pragma unroll
        for (int i = 0; i < 2; i++) {
            int idx = tid + i * 256, r = idx >> 3, c = idx & 7;
            cp16s(smK + s * 8192 + sw128(r * 128 + c * 16), Kb + (long)(kv0 + r) * HD + c * 8);
        }
        #pragma unroll
        for (int i = 0; i < 2; i++) {
            int idx = tid + i * 256, r = idx >> 3, c = idx & 7;
            cp16s(smV + s * 8192 + sw128(r * 128 + c * 16), Vb + (long)(kv0 + r) * HD + c * 8);
        }
        cp_commit();
    };
    load_kv(0, 0);
    load_kv(1, 1);   // nkv >= 2 always

    cp_wait<2>();    // Q done (K/V tiles 0,1 may still be in flight)
    __syncthreads();
    uint32_t qf[4][4];
    #pragma unroll
    for (int kc = 0; kc < 4; kc++)
        ldsm4(qf[kc], smQ + sw128((w * 16 + aRow) * 128 + (kc * 2 + aChk) * 16));

    float oacc[8][4] = {};
    float m0 = -INFINITY, m1 = -INFINITY, l0 = 0.0f, l1 = 0.0f;
    const int r0g = row0 + w * 16 + g;
    const int r1g = r0g + 8;

    for (int it = 0; it < nkv; it++) {
        int s = it & 3;
        if (it + 2 < nkv) load_kv(it + 2, (it + 2) & 3); else cp_commit();
        cp_wait<2>();
        __syncthreads();

        uint32_t kS = smK + s * 8192, vS = smV + s * 8192;

        // ---- S = Q K^T ----
        float sacc[8][4] = {};
        #pragma unroll
        for (int kc = 0; kc < 4; kc++) {
            uint32_t bfr[8][2];
            #pragma unroll
            for (int j = 0; j < 4; j++) {
                uint32_t r4[4];
                ldsm4(r4, kS + sw128((j * 16 + bRow) * 128 + (kc * 2 + bChk) * 16));
                bfr[2*j][0] = r4[0]; bfr[2*j][1] = r4[1];
                bfr[2*j+1][0] = r4[2]; bfr[2*j+1][1] = r4[3];
            }
            #pragma unroll
            for (int ni = 0; ni < 8; ni++)
                mma16816(sacc[ni], qf[kc], bfr[ni]);
        }

        // ---- scale + causal mask + online softmax ----
        const int kv0 = it * 64;
        const bool needmask = (kv0 + 63) > (row0 + w * 16);
        float tm0 = -INFINITY, tm1 = -INFINITY;
        #pragma unroll
        for (int ni = 0; ni < 8; ni++) {
            float s0 = sacc[ni][0] * 0.125f, s1 = sacc[ni][1] * 0.125f;
            float s2 = sacc[ni][2] * 0.125f, s3 = sacc[ni][3] * 0.125f;
            if (needmask) {
                int col = kv0 + ni * 8 + tig * 2;
                if (col     > r0g) s0 = -1e30f;
                if (col + 1 > r0g) s1 = -1e30f;
                if (col     > r1g) s2 = -1e30f;
                if (col + 1 > r1g) s3 = -1e30f;
            }
            sacc[ni][0] = s0; sacc[ni][1] = s1; sacc[ni][2] = s2; sacc[ni][3] = s3;
            tm0 = fmaxf(tm0, fmaxf(s0, s1));
            tm1 = fmaxf(tm1, fmaxf(s2, s3));
        }
        #pragma unroll
        for (int o = 1; o <= 2; o <<= 1) {
            tm0 = fmaxf(tm0, __shfl_xor_sync(0xffffffffu, tm0, o));
            tm1 = fmaxf(tm1, __shfl_xor_sync(0xffffffffu, tm1, o));
        }
        float mn0 = fmaxf(m0, tm0), mn1 = fmaxf(m1, tm1);
        float f0 = __expf(m0 - mn0), f1 = __expf(m1 - mn1);
        m0 = mn0; m1 = mn1;

        uint32_t ph[8][2];
        float ls0 = 0.0f, ls1 = 0.0f;
        #pragma unroll
        for (int ni = 0; ni < 8; ni++) {
            float p0 = __expf(sacc[ni][0] - mn0), p1 = __expf(sacc[ni][1] - mn0);
            float p2 = __expf(sacc[ni][2] - mn1), p3 = __expf(sacc[ni][3] - mn1);
            ls0 += p0 + p1; ls1 += p2 + p3;
            ph[ni][0] = h2_u32(__floats2half2_rn(p0, p1));
            ph[ni][1] = h2_u32(__floats2half2_rn(p2, p3));
        }
        l0 = l0 * f0 + ls0;
        l1 = l1 * f1 + ls1;
        #pragma unroll
        for (int ni = 0; ni < 8; ni++) {
            oacc[ni][0] *= f0; oacc[ni][1] *= f0;
            oacc[ni][2] *= f1; oacc[ni][3] *= f1;
        }

        // ---- O += P @ V ----
        #pragma unroll
        for (int kc = 0; kc < 4; kc++) {
            uint32_t a[4] = { ph[2*kc][0], ph[2*kc][1], ph[2*kc+1][0], ph[2*kc+1][1] };
            uint32_t vb[8][2];
            #pragma unroll
            for (int j = 0; j < 4; j++) {
                uint32_t r4[4];
                ldsm4t(r4, vS + sw128((kc * 16 + aRow) * 128 + (2 * j + aChk) * 16));
                vb[2*j][0] = r4[0]; vb[2*j][1] = r4[1];
                vb[2*j+1][0] = r4[2]; vb[2*j+1][1] = r4[3];
            }
            #pragma unroll
            for (int nj = 0; nj < 8; nj++)
                mma16816(oacc[nj], a, vb[nj]);
        }
        // no trailing barrier: 4-slot ring separates slot reuse by two
        // top-of-loop barriers (prefetch at it targets slot (it+2)&3,
        // last consumed at it-2, fully retired before barrier of it-1).
    }

    // ---- finalize ----
    #pragma unroll
    for (int o = 1; o <= 2; o <<= 1) {
        l0 += __shfl_xor_sync(0xffffffffu, l0, o);
        l1 += __shfl_xor_sync(0xffffffffu, l1, o);
    }
    float i0 = 1.0f / l0, i1 = 1.0f / l1;
    __half* Ob = O + ((long)(b << 10)) * EMB;
    #pragma unroll
    for (int ni = 0; ni < 8; ni++) {
        int col = hh * HD + ni * 8 + tig * 2;
        *(__half2*)&Ob[(long)r0g * EMB + col] = __floats2half2_rn(oacc[ni][0] * i0, oacc[ni][1] * i0);
        *(__half2*)&Ob[(long)r1g * EMB + col] = __floats2half2_rn(oacc[ni][2] * i1, oacc[ni][3] * i1);
    }
}

// ---------------------------------------------------------------------------
// fp16 tensor-core GEMM (m16n8k16, ldmatrix, SW128, 3-stage cp.async), NT:
//   C[m,n] = sum_k A[m,k] * B[n,k].  256 threads = 8 warps, MINB CTAs/SM.
// ---------------------------------------------------------------------------
#define EPI_QKV3   0
#define EPI_RES    5
#define EPI_GELU   6

template<int BM, int BN, int WM, int WN, int EPI, int MINB>
__global__ void __launch_bounds__(256, MINB)
gemm_h(const __half* __restrict__ A, const __half* __restrict__ Bm,
       const float* __restrict__ R, void* __restrict__ Cv,
       int M, int N, int K) {
    constexpr int BK  = 64;
    constexpr int WTM = BM / WM, WTN = BN / WN;
    constexpr int MF  = WTM / 16, NF = WTN / 8;
    constexpr int A_STG = BM * BK * 2;
    constexpr int B_STG = BN * BK * 2;

    const int tid  = threadIdx.x;
    const int row0 = blockIdx.y * BM;
    const int col0 = blockIdx.x * BN;

    extern __shared__ char smraw[];
    const uint32_t smA = (uint32_t)__cvta_generic_to_shared(smraw);
    const uint32_t smB = smA + 3 * A_STG;

    auto load_tile = [&](int k0, int s) {
        uint32_t aB = smA + s * A_STG;
        #pragma unroll
        for (int i = 0; i < BM * 8 / 256; i++) {
            int idx = tid + i * 256, r = idx >> 3, c = idx & 7;
            cp16s(aB + sw128(r * 128 + c * 16), A + (long)(row0 + r) * K + k0 + c * 8);
        }
        uint32_t bB = smB + s * B_STG;
        #pragma unroll
        for (int i = 0; i < BN * 8 / 256; i++) {
            int idx = tid + i * 256, r = idx >> 3, c = idx & 7;
            cp16s(bB + sw128(r * 128 + c * 16), Bm + (long)(col0 + r) * K + k0 + c * 8);
        }
        cp_commit();
    };

    const int lane = tid & 31, w = tid >> 5;
    const int g = lane >> 2, tig = lane & 3;
    const int rw = (w % WM) * WTM, cw = (w / WM) * WTN;
    const int aRow = (lane & 7) + ((lane >> 3) & 1) * 8, aChk = lane >> 4;
    const int bRow = (lane & 7) + (lane >> 4) * 8,       bChk = (lane >> 3) & 1;

    float acc[MF][NF][4] = {};

    const int nt = K / BK;
    load_tile(0, 0);
    if (nt > 1) load_tile(BK, 1); else cp_commit();

    for (int it = 0; it < nt; it++) {
        int s = it % 3;
        if (it + 2 < nt) load_tile((it + 2) * BK, (it + 2) % 3); else cp_commit();
        cp_wait<2>();
        __syncthreads();
        uint32_t aS = smA + s * A_STG, bS = smB + s * B_STG;

        #pragma unroll
        for (int kk = 0; kk < BK; kk += 16) {
            uint32_t afr[MF][4];
            #pragma unroll
            for (int mi = 0; mi < MF; mi++)
                ldsm4(afr[mi], aS + sw128((rw + mi * 16 + aRow) * 128 + ((kk >> 3) + aChk) * 16));
            uint32_t bfr[NF][2];
            #pragma unroll
            for (int j = 0; j < NF / 2; j++) {
                uint32_t r4[4];
                ldsm4(r4, bS + sw128((cw + j * 16 + bRow) * 128 + ((kk >> 3) + bChk) * 16));
                bfr[2*j][0] = r4[0]; bfr[2*j][1] = r4[1];
                bfr[2*j+1][0] = r4[2]; bfr[2*j+1][1] = r4[3];
            }
            #pragma unroll
            for (int mi = 0; mi < MF; mi++)
                #pragma unroll
                for (int ni = 0; ni < NF; ni++)
                    mma16816(acc[mi][ni], afr[mi], bfr[ni]);
        }
        __syncthreads();
    }

    // ---------------- epilogue ----------------
    #pragma unroll
    for (int mi = 0; mi < MF; mi++) {
        #pragma unroll
        for (int ni = 0; ni < NF; ni++) {
            int r_ = row0 + rw + mi * 16 + g;
            int c_ = col0 + cw + ni * 8 + tig * 2;
            float* a4 = acc[mi][ni];
            #pragma unroll
            for (int half = 0; half < 2; half++) {
                int rr = r_ + half * 8;
                float v0 = a4[half * 2 + 0];
                float v1 = a4[half * 2 + 1];

                if (EPI == EPI_QKV3) {
                    __half* Cp = (__half*)Cv;
                    int seg = c_ / EMB;
                    int cn  = c_ - seg * EMB;
                    int b = rr >> 10, t = rr & 1023;
                    int h = cn >> 6,  d = cn & 63;
                    long o = (long)seg * (NTOK * EMB)
                           + (((long)(b * NH + h) << 10) + t) * HD + d;
                    *(__half2*)&Cp[o] = __floats2half2_rn(v0, v1);
                } else if (EPI == EPI_RES) {
                    float* Cp = (float*)Cv;
                    long o = (long)rr * N + c_;
                    float2 rv = *(const float2*)&R[o];
                    *(float2*)&Cp[o] = make_float2(v0 + rv.x, v1 + rv.y);
                } else if (EPI == EPI_GELU) {
                    __half* Cp = (__half*)Cv;
                    // gelu_tanh(x) = x * sigmoid(2c(x + 0.044715 x^3)), exact identity
                    float y0 = 1.5957691216057308f * (v0 + 0.044715f * v0 * v0 * v0);
                    float y1 = 1.5957691216057308f * (v1 + 0.044715f * v1 * v1 * v1);
                    float g0 = v0 / (1.0f + __expf(-y0));
                    float g1 = v1 / (1.0f + __expf(-y1));
                    *(__half2*)&Cp[(long)rr * N + c_] = __floats2half2_rn(g0, g1);
                }
            }
        }
    }
}

// ---------------------------------------------------------------------------
// Launch
// ---------------------------------------------------------------------------
extern "C" void kernel_launch(void* const* d_in, const int* in_sizes, int n_in,
                              void* d_out, int out_size) {
    const float* x    = (const float*)d_in[0];
    const float* wq   = (const float*)d_in[1];
    const float* wk   = (const float*)d_in[2];
    const float* wv   = (const float*)d_in[3];
    const float* wo   = (const float*)d_in[4];
    const float* w1   = (const float*)d_in[5];
    const float* w2   = (const float*)d_in[6];
    const float* ln1s = (const float*)d_in[7];
    const float* ln1b = (const float*)d_in[8];
    const float* ln2s = (const float*)d_in[9];
    const float* ln2b = (const float*)d_in[10];
    float* out = (float*)d_out;

    __half *h16, *qkv16, *ctx16, *ffn16, *wqkv16, *wo16, *w116, *w216;
    float* x2;
    cudaGetSymbolAddress((void**)&h16,    g_h16);
    cudaGetSymbolAddress((void**)&qkv16,  g_qkv16);
    cudaGetSymbolAddress((void**)&ctx16,  g_ctx16);
    cudaGetSymbolAddress((void**)&ffn16,  g_ffn16);
    cudaGetSymbolAddress((void**)&x2,     g_x2);
    cudaGetSymbolAddress((void**)&wqkv16, g_wqkv16);
    cudaGetSymbolAddress((void**)&wo16,   g_wo16);
    cudaGetSymbolAddress((void**)&w116,   g_w116);
    cudaGetSymbolAddress((void**)&w216,   g_w216);

    __half* q16 = qkv16;
    __half* k16 = qkv16 + (long)NTOK * EMB;
    __half* v16 = qkv16 + 2L * NTOK * EMB;

    constexpr int SM_NT    = 3 * (128 * 64 + 128 * 64) * 2;    // 98304 B
    constexpr int SM_SMALL = 3 * (64 * 64 + 128 * 64) * 2;     // 73728 B
    constexpr int SM_FLASH = 128 * 128 + 2 * 4 * 64 * 128 * 2; // 16K + 64K = 81920 B

    cudaFuncSetAttribute(gemm_h<128,128,2,4,EPI_QKV3,2>,
                         cudaFuncAttributeMaxDynamicSharedMemorySize, SM_NT);
    cudaFuncSetAttribute(gemm_h<64,128,2,4,EPI_RES,3>,
                         cudaFuncAttributeMaxDynamicSharedMemorySize, SM_SMALL);
    cudaFuncSetAttribute(gemm_h<128,128,2,4,EPI_GELU,2>,
                         cudaFuncAttributeMaxDynamicSharedMemorySize, SM_NT);
    cudaFuncSetAttribute(flash_k,
                         cudaFuncAttributeMaxDynamicSharedMemorySize, SM_FLASH);

    // 0) all weight fp32 -> fp16 conversions in one launch
    f2h_all_k<<<dim3(FFND * EMB / 1024, 6), 256>>>(
        wq, wk, wv, wo, w1, w2, wqkv16, wo16, w116, w216);

    // 1) LN1 (fp32 -> fp16), warp-per-row
    layernorm_k<<<NTOK / 8, 256>>>(x, h16, ln1s, ln1b);

    // 2) fused QKV projection : M=8192, N=2304, K=768 -> q|k|v [B,H,T,D]
    gemm_h<128,128,2,4,EPI_QKV3,2><<<dim3(3 * EMB / 128, NTOK / 128), 256, SM_NT>>>(
        h16, wqkv16, nullptr, qkv16, NTOK, 3 * EMB, EMB);

    // 3) flash attention -> ctx fp16 [B,T,E]
    flash_k<<<dim3(Tseq / 128, Bsz * NH), 256, SM_FLASH>>>(q16, k16, v16, ctx16);

    // 4) x2 = x + ctx @ Wo^T (fp32 residual) : 64-row tiles, 3 CTAs/SM
    gemm_h<64,128,2,4,EPI_RES,3><<<dim3(EMB / 128, NTOK / 64), 256, SM_SMALL>>>(
        ctx16, wo16, x, x2, NTOK, EMB, EMB);

    // 5) LN2 (fp32 -> fp16), warp-per-row
    layernorm_k<<<NTOK / 8, 256>>>(x2, h16, ln2s, ln2b);

    // 6) ffn = gelu(h @ W1^T) fp16 : M=8192, N=3072, K=768
    gemm_h<128,128,2,4,EPI_GELU,2><<<dim3(FFND / 128, NTOK / 128), 256, SM_NT>>>(
        h16, w116, nullptr, ffn16, NTOK, FFND, EMB);

    // 7) out = x2 + ffn @ W2^T (fp32 residual) : 64-row tiles, 3 CTAs/SM
    gemm_h<64,128,2,4,EPI_RES,3><<<dim3(EMB / 128, NTOK / 64), 256, SM_SMALL>>>(
        ffn16, w216, x2, out, NTOK, EMB, FFND);
}

// round 13
// speedup vs baseline: 1.0959x; 1.0959x over previous
#include <cuda_runtime.h>
#include <cuda_fp16.h>
#include <math.h>
#include <stdint.h>

// ---------------------------------------------------------------------------
// Problem constants
// ---------------------------------------------------------------------------
#define Bsz   8
#define Tseq  1024
#define EMB   768
#define NH    12
#define HD    64
#define NTOK  (Bsz * Tseq)          // 8192
#define FFND  (4 * EMB)             // 3072

// ---------------------------------------------------------------------------
// Scratch (device globals — allocation-free)
// ---------------------------------------------------------------------------
__device__ __half g_h16  [NTOK * EMB];                 // LN output (fp16)
__device__ __half g_qkv16[3L * NTOK * EMB];            // q|k|v, each [B,H,T,D]
__device__ __half g_ctx16[NTOK * EMB];                 // [B,T,E]
__device__ __half g_ffn16[NTOK * FFND];                // gelu(h @ W1^T)
__device__ float  g_x2   [NTOK * EMB];                 // fp32 residual stream
// fp16 weight copies
__device__ __half g_wqkv16[3 * EMB * EMB];             // wq|wk|wv rows
__device__ __half g_wo16[EMB * EMB];
__device__ __half g_w116[FFND * EMB];
__device__ __half g_w216[EMB * FFND];

// ---------------------------------------------------------------------------
// PTX helpers
// ---------------------------------------------------------------------------
__device__ __forceinline__ void cp16s(uint32_t dst, const void* src) {
    asm volatile("cp.async.ca.shared.global [%0], [%1], 16;" :: "r"(dst), "l"(src));
}
__device__ __forceinline__ void cp_commit() {
    asm volatile("cp.async.commit_group;" ::: "memory");
}
template<int N>
__device__ __forceinline__ void cp_wait() {
    asm volatile("cp.async.wait_group %0;" :: "n"(N) : "memory");
}
__device__ __forceinline__ uint32_t sw128(uint32_t o) {   // Swizzle<3,4,3>, 128B rows
    return o ^ ((o >> 3) & 0x70);
}
__device__ __forceinline__ uint32_t h2_u32(__half2 h) {
    return *reinterpret_cast<uint32_t*>(&h);
}
__device__ __forceinline__ void ldsm4(uint32_t* r, uint32_t addr) {
    asm volatile("ldmatrix.sync.aligned.m8n8.x4.shared.b16 {%0,%1,%2,%3}, [%4];"
        : "=r"(r[0]), "=r"(r[1]), "=r"(r[2]), "=r"(r[3]) : "r"(addr));
}
__device__ __forceinline__ void ldsm4t(uint32_t* r, uint32_t addr) {
    asm volatile("ldmatrix.sync.aligned.m8n8.x4.trans.shared.b16 {%0,%1,%2,%3}, [%4];"
        : "=r"(r[0]), "=r"(r[1]), "=r"(r[2]), "=r"(r[3]) : "r"(addr));
}
__device__ __forceinline__ void mma16816(float* d, const uint32_t* a, const uint32_t* b) {
    asm volatile(
        "mma.sync.aligned.m16n8k16.row.col.f32.f16.f16.f32 "
        "{%0,%1,%2,%3}, {%4,%5,%6,%7}, {%8,%9}, {%0,%1,%2,%3};"
        : "+f"(d[0]), "+f"(d[1]), "+f"(d[2]), "+f"(d[3])
        : "r"(a[0]), "r"(a[1]), "r"(a[2]), "r"(a[3]), "r"(b[0]), "r"(b[1]));
}

// ---------------------------------------------------------------------------
// Merged fp32 -> fp16 weight converter. blockIdx.y selects segment.
// ---------------------------------------------------------------------------
__global__ void f2h_all_k(const float* __restrict__ wq, const float* __restrict__ wk,
                          const float* __restrict__ wv, const float* __restrict__ wo,
                          const float* __restrict__ w1, const float* __restrict__ w2,
                          __half* __restrict__ dqkv, __half* __restrict__ dwo,
                          __half* __restrict__ dw1, __half* __restrict__ dw2) {
    const int seg = blockIdx.y;
    const int nblk = (seg < 4) ? (EMB * EMB / 1024) : (FFND * EMB / 1024);
    if (blockIdx.x >= nblk) return;
    const float* s;
    __half* d;
    switch (seg) {
        case 0: s = wq; d = dqkv;                 break;
        case 1: s = wk; d = dqkv + EMB * EMB;     break;
        case 2: s = wv; d = dqkv + 2 * EMB * EMB; break;
        case 3: s = wo; d = dwo;                  break;
        case 4: s = w1; d = dw1;                  break;
        default: s = w2; d = dw2;                 break;
    }
    int i = (blockIdx.x * 256 + threadIdx.x) * 4;
    float4 v = *(const float4*)(s + i);
    *(__half2*)(d + i)     = __floats2half2_rn(v.x, v.y);
    *(__half2*)(d + i + 2) = __floats2half2_rn(v.z, v.w);
}

// ---------------------------------------------------------------------------
// LayerNorm, warp-per-row (no block barriers): fp32 in, fp16 out.
// 256 threads = 8 warps = 8 rows per block; 1024 blocks.
// ---------------------------------------------------------------------------
__global__ void layernorm_k(const float* __restrict__ x, __half* __restrict__ o,
                            const float* __restrict__ sc, const float* __restrict__ sh) {
    const int lane = threadIdx.x & 31;
    const long row = (long)blockIdx.x * 8 + (threadIdx.x >> 5);
    const float4* p = (const float4*)(x + row * EMB);
    const float4* s4 = (const float4*)sc;
    const float4* b4 = (const float4*)sh;
    uint2* q = (uint2*)(o + row * EMB);

    float4 v[6];
    float sum = 0.0f, sq = 0.0f;
    #pragma unroll
    for (int j = 0; j < 6; j++) {
        v[j] = p[lane + 32 * j];
        sum += v[j].x + v[j].y + v[j].z + v[j].w;
        sq  += v[j].x * v[j].x + v[j].y * v[j].y + v[j].z * v[j].z + v[j].w * v[j].w;
    }
    #pragma unroll
    for (int ofs = 16; ofs; ofs >>= 1) {
        sum += __shfl_xor_sync(0xffffffffu, sum, ofs);
        sq  += __shfl_xor_sync(0xffffffffu, sq,  ofs);
    }
    float mean = sum * (1.0f / EMB);
    float var  = sq * (1.0f / EMB) - mean * mean;
    float rstd = rsqrtf(var + 1e-5f);

    #pragma unroll
    for (int j = 0; j < 6; j++) {
        float4 sv = s4[lane + 32 * j];
        float4 bv = b4[lane + 32 * j];
        __half2 h0 = __floats2half2_rn((v[j].x - mean) * rstd * sv.x + bv.x,
                                       (v[j].y - mean) * rstd * sv.y + bv.y);
        __half2 h1 = __floats2half2_rn((v[j].z - mean) * rstd * sv.z + bv.z,
                                       (v[j].w - mean) * rstd * sv.w + bv.w);
        q[lane + 32 * j] = make_uint2(h2_u32(h0), h2_u32(h1));
    }
}

// ---------------------------------------------------------------------------
// Flash attention: fused QK^T -> causal online softmax -> @V.
// 3-slot K/V ring (64 KB smem -> 2 CTAs/SM), prefetch distance 2.
// Heavy q-tiles scheduled first.
// ---------------------------------------------------------------------------
__global__ void __launch_bounds__(256, 2)
flash_k(const __half* __restrict__ Qg, const __half* __restrict__ Kg,
        const __half* __restrict__ Vg, __half* __restrict__ O) {
    const int qt  = gridDim.x - 1 - blockIdx.x;     // heavy tiles first
    const int bh  = blockIdx.y;
    const int row0 = qt * 128;
    const int b = bh / NH, hh = bh % NH;

    extern __shared__ char smraw[];
    const uint32_t smQ = (uint32_t)__cvta_generic_to_shared(smraw);   // 16 KB
    const uint32_t smK = smQ + 128 * 128;                             // 3 x 8 KB
    const uint32_t smV = smK + 3 * 64 * 128;                          // 3 x 8 KB

    const int tid = threadIdx.x, lane = tid & 31, w = tid >> 5;
    const int g = lane >> 2, tig = lane & 3;
    const int aRow = (lane & 7) + ((lane >> 3) & 1) * 8, aChk = lane >> 4;
    const int bRow = (lane & 7) + (lane >> 4) * 8,       bChk = (lane >> 3) & 1;

    const __half* Qb = Qg + ((long)bh << 10) * HD;
    const __half* Kb = Kg + ((long)bh << 10) * HD;
    const __half* Vb = Vg + ((long)bh << 10) * HD;

    for (int i = tid; i < 128 * 8; i += 256) {
        int r = i >> 3, c = i & 7;
        cp16s(smQ + sw128(r * 128 + c * 16), Qb + (long)(row0 + r) * HD + c * 8);
    }
    cp_commit();

    const int nkv = 2 * qt + 2;
    auto load_kv = [&](int it, int s) {
        int kv0 = it * 64;
        #pragma unroll
        for (int i = 0; i < 2; i++) {
            int idx = tid + i * 256, r = idx >> 3, c = idx & 7;
            cp16s(smK + s * 8192 + sw128(r * 128 + c * 16), Kb + (long)(kv0 + r) * HD + c * 8);
        }
        #pragma unroll
        for (int i = 0; i < 2; i++) {
            int idx = tid + i * 256, r = idx >> 3, c = idx & 7;
            cp16s(smV + s * 8192 + sw128(r * 128 + c * 16), Vb + (long)(kv0 + r) * HD + c * 8);
        }
        cp_commit();
    };
    load_kv(0, 0);
    load_kv(1, 1);   // nkv >= 2 always

    cp_wait<2>();
    __syncthreads();
    uint32_t qf[4][4];
    #pragma unroll
    for (int kc = 0; kc < 4; kc++)
        ldsm4(qf[kc], smQ + sw128((w * 16 + aRow) * 128 + (kc * 2 + aChk) * 16));

    float oacc[8][4] = {};
    float m0 = -INFINITY, m1 = -INFINITY, l0 = 0.0f, l1 = 0.0f;
    const int r0g = row0 + w * 16 + g;
    const int r1g = r0g + 8;

    for (int it = 0; it < nkv; it++) {
        int s = it % 3;
        if (it + 2 < nkv) load_kv(it + 2, (it + 2) % 3); else cp_commit();
        cp_wait<2>();
        __syncthreads();

        uint32_t kS = smK + s * 8192, vS = smV + s * 8192;

        // ---- S = Q K^T ----
        float sacc[8][4] = {};
        #pragma unroll
        for (int kc = 0; kc < 4; kc++) {
            uint32_t bfr[8][2];
            #pragma unroll
            for (int j = 0; j < 4; j++) {
                uint32_t r4[4];
                ldsm4(r4, kS + sw128((j * 16 + bRow) * 128 + (kc * 2 + bChk) * 16));
                bfr[2*j][0] = r4[0]; bfr[2*j][1] = r4[1];
                bfr[2*j+1][0] = r4[2]; bfr[2*j+1][1] = r4[3];
            }
            #pragma unroll
            for (int ni = 0; ni < 8; ni++)
                mma16816(sacc[ni], qf[kc], bfr[ni]);
        }

        // ---- scale + causal mask + online softmax ----
        const int kv0 = it * 64;
        const bool needmask = (kv0 + 63) > (row0 + w * 16);
        float tm0 = -INFINITY, tm1 = -INFINITY;
        #pragma unroll
        for (int ni = 0; ni < 8; ni++) {
            float s0 = sacc[ni][0] * 0.125f, s1 = sacc[ni][1] * 0.125f;
            float s2 = sacc[ni][2] * 0.125f, s3 = sacc[ni][3] * 0.125f;
            if (needmask) {
                int col = kv0 + ni * 8 + tig * 2;
                if (col     > r0g) s0 = -1e30f;
                if (col + 1 > r0g) s1 = -1e30f;
                if (col     > r1g) s2 = -1e30f;
                if (col + 1 > r1g) s3 = -1e30f;
            }
            sacc[ni][0] = s0; sacc[ni][1] = s1; sacc[ni][2] = s2; sacc[ni][3] = s3;
            tm0 = fmaxf(tm0, fmaxf(s0, s1));
            tm1 = fmaxf(tm1, fmaxf(s2, s3));
        }
        #pragma unroll
        for (int o = 1; o <= 2; o <<= 1) {
            tm0 = fmaxf(tm0, __shfl_xor_sync(0xffffffffu, tm0, o));
            tm1 = fmaxf(tm1, __shfl_xor_sync(0xffffffffu, tm1, o));
        }
        float mn0 = fmaxf(m0, tm0), mn1 = fmaxf(m1, tm1);
        float f0 = __expf(m0 - mn0), f1 = __expf(m1 - mn1);
        m0 = mn0; m1 = mn1;

        uint32_t ph[8][2];
        float ls0 = 0.0f, ls1 = 0.0f;
        #pragma unroll
        for (int ni = 0; ni < 8; ni++) {
            float p0 = __expf(sacc[ni][0] - mn0), p1 = __expf(sacc[ni][1] - mn0);
            float p2 = __expf(sacc[ni][2] - mn1), p3 = __expf(sacc[ni][3] - mn1);
            ls0 += p0 + p1; ls1 += p2 + p3;
            ph[ni][0] = h2_u32(__floats2half2_rn(p0, p1));
            ph[ni][1] = h2_u32(__floats2half2_rn(p2, p3));
        }
        l0 = l0 * f0 + ls0;
        l1 = l1 * f1 + ls1;
        #pragma unroll
        for (int ni = 0; ni < 8; ni++) {
            oacc[ni][0] *= f0; oacc[ni][1] *= f0;
            oacc[ni][2] *= f1; oacc[ni][3] *= f1;
        }

        // ---- O += P @ V ----
        #pragma unroll
        for (int kc = 0; kc < 4; kc++) {
            uint32_t a[4] = { ph[2*kc][0], ph[2*kc][1], ph[2*kc+1][0], ph[2*kc+1][1] };
            uint32_t vb[8][2];
            #pragma unroll
            for (int j = 0; j < 4; j++) {
                uint32_t r4[4];
                ldsm4t(r4, vS + sw128((kc * 16 + aRow) * 128 + (2 * j + aChk) * 16));
                vb[2*j][0] = r4[0]; vb[2*j][1] = r4[1];
                vb[2*j+1][0] = r4[2]; vb[2*j+1][1] = r4[3];
            }
            #pragma unroll
            for (int nj = 0; nj < 8; nj++)
                mma16816(oacc[nj], a, vb[nj]);
        }
        __syncthreads();
    }

    // ---- finalize ----
    #pragma unroll
    for (int o = 1; o <= 2; o <<= 1) {
        l0 += __shfl_xor_sync(0xffffffffu, l0, o);
        l1 += __shfl_xor_sync(0xffffffffu, l1, o);
    }
    float i0 = 1.0f / l0, i1 = 1.0f / l1;
    __half* Ob = O + ((long)(b << 10)) * EMB;
    #pragma unroll
    for (int ni = 0; ni < 8; ni++) {
        int col = hh * HD + ni * 8 + tig * 2;
        *(__half2*)&Ob[(long)r0g * EMB + col] = __floats2half2_rn(oacc[ni][0] * i0, oacc[ni][1] * i0);
        *(__half2*)&Ob[(long)r1g * EMB + col] = __floats2half2_rn(oacc[ni][2] * i1, oacc[ni][3] * i1);
    }
}

// ---------------------------------------------------------------------------
// fp16 tensor-core GEMM (m16n8k16, ldmatrix, SW128, 3-stage cp.async), NT:
//   C[m,n] = sum_k A[m,k] * B[n,k].  256 threads = 8 warps, 2 CTAs/SM.
// ---------------------------------------------------------------------------
#define EPI_QKV3   0
#define EPI_RES    5
#define EPI_GELU   6

template<int BM, int BN, int WM, int WN, int EPI>
__global__ void __launch_bounds__(256, 2)
gemm_h(const __half* __restrict__ A, const __half* __restrict__ Bm,
       const float* __restrict__ R, void* __restrict__ Cv,
       int M, int N, int K) {
    constexpr int BK  = 64;
    constexpr int WTM = BM / WM, WTN = BN / WN;
    constexpr int MF  = WTM / 16, NF = WTN / 8;
    constexpr int A_STG = BM * BK * 2;
    constexpr int B_STG = BN * BK * 2;

    const int tid  = threadIdx.x;
    const int row0 = blockIdx.y * BM;
    const int col0 = blockIdx.x * BN;

    extern __shared__ char smraw[];
    const uint32_t smA = (uint32_t)__cvta_generic_to_shared(smraw);
    const uint32_t smB = smA + 3 * A_STG;

    auto load_tile = [&](int k0, int s) {
        uint32_t aB = smA + s * A_STG;
        #pragma unroll
        for (int i = 0; i < BM * 8 / 256; i++) {
            int idx = tid + i * 256, r = idx >> 3, c = idx & 7;
            cp16s(aB + sw128(r * 128 + c * 16), A + (long)(row0 + r) * K + k0 + c * 8);
        }
        uint32_t bB = smB + s * B_STG;
        #pragma unroll
        for (int i = 0; i < BN * 8 / 256; i++) {
            int idx = tid + i * 256, r = idx >> 3, c = idx & 7;
            cp16s(bB + sw128(r * 128 + c * 16), Bm + (long)(col0 + r) * K + k0 + c * 8);
        }
        cp_commit();
    };

    const int lane = tid & 31, w = tid >> 5;
    const int g = lane >> 2, tig = lane & 3;
    const int rw = (w % WM) * WTM, cw = (w / WM) * WTN;
    const int aRow = (lane & 7) + ((lane >> 3) & 1) * 8, aChk = lane >> 4;
    const int bRow = (lane & 7) + (lane >> 4) * 8,       bChk = (lane >> 3) & 1;

    float acc[MF][NF][4] = {};

    const int nt = K / BK;
    load_tile(0, 0);
    if (nt > 1) load_tile(BK, 1); else cp_commit();

    for (int it = 0; it < nt; it++) {
        int s = it % 3;
        if (it + 2 < nt) load_tile((it + 2) * BK, (it + 2) % 3); else cp_commit();
        cp_wait<2>();
        __syncthreads();
        uint32_t aS = smA + s * A_STG, bS = smB + s * B_STG;

        #pragma unroll
        for (int kk = 0; kk < BK; kk += 16) {
            uint32_t afr[MF][4];
            #pragma unroll
            for (int mi = 0; mi < MF; mi++)
                ldsm4(afr[mi], aS + sw128((rw + mi * 16 + aRow) * 128 + ((kk >> 3) + aChk) * 16));
            uint32_t bfr[NF][2];
            #pragma unroll
            for (int j = 0; j < NF / 2; j++) {
                uint32_t r4[4];
                ldsm4(r4, bS + sw128((cw + j * 16 + bRow) * 128 + ((kk >> 3) + bChk) * 16));
                bfr[2*j][0] = r4[0]; bfr[2*j][1] = r4[1];
                bfr[2*j+1][0] = r4[2]; bfr[2*j+1][1] = r4[3];
            }
            #pragma unroll
            for (int mi = 0; mi < MF; mi++)
                #pragma unroll
                for (int ni = 0; ni < NF; ni++)
                    mma16816(acc[mi][ni], afr[mi], bfr[ni]);
        }
        __syncthreads();
    }

    // ---------------- epilogue ----------------
    #pragma unroll
    for (int mi = 0; mi < MF; mi++) {
        #pragma unroll
        for (int ni = 0; ni < NF; ni++) {
            int r_ = row0 + rw + mi * 16 + g;
            int c_ = col0 + cw + ni * 8 + tig * 2;
            float* a4 = acc[mi][ni];
            #pragma unroll
            for (int half = 0; half < 2; half++) {
                int rr = r_ + half * 8;
                float v0 = a4[half * 2 + 0];
                float v1 = a4[half * 2 + 1];

                if (EPI == EPI_QKV3) {
                    __half* Cp = (__half*)Cv;
                    int seg = c_ / EMB;
                    int cn  = c_ - seg * EMB;
                    int b = rr >> 10, t = rr & 1023;
                    int h = cn >> 6,  d = cn & 63;
                    long o = (long)seg * (NTOK * EMB)
                           + (((long)(b * NH + h) << 10) + t) * HD + d;
                    *(__half2*)&Cp[o] = __floats2half2_rn(v0, v1);
                } else if (EPI == EPI_RES) {
                    float* Cp = (float*)Cv;
                    long o = (long)rr * N + c_;
                    float2 rv = *(const float2*)&R[o];
                    *(float2*)&Cp[o] = make_float2(v0 + rv.x, v1 + rv.y);
                } else if (EPI == EPI_GELU) {
                    __half* Cp = (__half*)Cv;
                    // gelu_tanh(x) = x * sigmoid(2c(x + 0.044715 x^3)), exact identity
                    float y0 = 1.5957691216057308f * (v0 + 0.044715f * v0 * v0 * v0);
                    float y1 = 1.5957691216057308f * (v1 + 0.044715f * v1 * v1 * v1);
                    float g0 = v0 / (1.0f + __expf(-y0));
                    float g1 = v1 / (1.0f + __expf(-y1));
                    *(__half2*)&Cp[(long)rr * N + c_] = __floats2half2_rn(g0, g1);
                }
            }
        }
    }
}

// ---------------------------------------------------------------------------
// Launch
// ---------------------------------------------------------------------------
extern "C" void kernel_launch(void* const* d_in, const int* in_sizes, int n_in,
                              void* d_out, int out_size) {
    const float* x    = (const float*)d_in[0];
    const float* wq   = (const float*)d_in[1];
    const float* wk   = (const float*)d_in[2];
    const float* wv   = (const float*)d_in[3];
    const float* wo   = (const float*)d_in[4];
    const float* w1   = (const float*)d_in[5];
    const float* w2   = (const float*)d_in[6];
    const float* ln1s = (const float*)d_in[7];
    const float* ln1b = (const float*)d_in[8];
    const float* ln2s = (const float*)d_in[9];
    const float* ln2b = (const float*)d_in[10];
    float* out = (float*)d_out;

    __half *h16, *qkv16, *ctx16, *ffn16, *wqkv16, *wo16, *w116, *w216;
    float* x2;
    cudaGetSymbolAddress((void**)&h16,    g_h16);
    cudaGetSymbolAddress((void**)&qkv16,  g_qkv16);
    cudaGetSymbolAddress((void**)&ctx16,  g_ctx16);
    cudaGetSymbolAddress((void**)&ffn16,  g_ffn16);
    cudaGetSymbolAddress((void**)&x2,     g_x2);
    cudaGetSymbolAddress((void**)&wqkv16, g_wqkv16);
    cudaGetSymbolAddress((void**)&wo16,   g_wo16);
    cudaGetSymbolAddress((void**)&w116,   g_w116);
    cudaGetSymbolAddress((void**)&w216,   g_w216);

    __half* q16 = qkv16;
    __half* k16 = qkv16 + (long)NTOK * EMB;
    __half* v16 = qkv16 + 2L * NTOK * EMB;

    constexpr int SM_NT    = 3 * (128 * 64 + 128 * 64) * 2;    // 98304 B
    constexpr int SM_FLASH = 128 * 128 + 2 * 3 * 64 * 128 * 2; // 65536 B

    cudaFuncSetAttribute(gemm_h<128,128,2,4,EPI_QKV3>,
                         cudaFuncAttributeMaxDynamicSharedMemorySize, SM_NT);
    cudaFuncSetAttribute(gemm_h<128,128,2,4,EPI_RES>,
                         cudaFuncAttributeMaxDynamicSharedMemorySize, SM_NT);
    cudaFuncSetAttribute(gemm_h<128,128,2,4,EPI_GELU>,
                         cudaFuncAttributeMaxDynamicSharedMemorySize, SM_NT);
    cudaFuncSetAttribute(flash_k,
                         cudaFuncAttributeMaxDynamicSharedMemorySize, SM_FLASH);

    // 0) all weight fp32 -> fp16 conversions in one launch
    f2h_all_k<<<dim3(FFND * EMB / 1024, 6), 256>>>(
        wq, wk, wv, wo, w1, w2, wqkv16, wo16, w116, w216);

    // 1) LN1 (fp32 -> fp16), warp-per-row
    layernorm_k<<<NTOK / 8, 256>>>(x, h16, ln1s, ln1b);

    // 2) fused QKV projection : M=8192, N=2304, K=768 -> q|k|v [B,H,T,D]
    gemm_h<128,128,2,4,EPI_QKV3><<<dim3(3 * EMB / 128, NTOK / 128), 256, SM_NT>>>(
        h16, wqkv16, nullptr, qkv16, NTOK, 3 * EMB, EMB);

    // 3) flash attention -> ctx fp16 [B,T,E]
    flash_k<<<dim3(Tseq / 128, Bsz * NH), 256, SM_FLASH>>>(q16, k16, v16, ctx16);

    // 4) x2 = x + ctx @ Wo^T (fp32 residual) : M=8192, N=768, K=768
    gemm_h<128,128,2,4,EPI_RES><<<dim3(EMB / 128, NTOK / 128), 256, SM_NT>>>(
        ctx16, wo16, x, x2, NTOK, EMB, EMB);

    // 5) LN2 (fp32 -> fp16), warp-per-row
    layernorm_k<<<NTOK / 8, 256>>>(x2, h16, ln2s, ln2b);

    // 6) ffn = gelu(h @ W1^T) fp16 : M=8192, N=3072, K=768
    gemm_h<128,128,2,4,EPI_GELU><<<dim3(FFND / 128, NTOK / 128), 256, SM_NT>>>(
        h16, w116, nullptr, ffn16, NTOK, FFND, EMB);

    // 7) out = x2 + ffn @ W2^T (fp32 residual) : M=8192, N=768, K=3072
    gemm_h<128,128,2,4,EPI_RES><<<dim3(EMB / 128, NTOK / 128), 256, SM_NT>>>(
        ffn16, w216, x2, out, NTOK, EMB, FFND);
}

// round 14
// speedup vs baseline: 1.1130x; 1.0157x over previous
#include <cuda_runtime.h>
#include <cuda_fp16.h>
#include <math.h>
#include <stdint.h>

// ---------------------------------------------------------------------------
// Problem constants
// ---------------------------------------------------------------------------
#define Bsz   8
#define Tseq  1024
#define EMB   768
#define NH    12
#define HD    64
#define NTOK  (Bsz * Tseq)          // 8192
#define FFND  (4 * EMB)             // 3072

// ---------------------------------------------------------------------------
// Scratch (device globals — allocation-free)
// ---------------------------------------------------------------------------
__device__ __half g_h16  [NTOK * EMB];                 // LN output (fp16)
__device__ __half g_qkv16[3L * NTOK * EMB];            // q|k|v, each [B,H,T,D]
__device__ __half g_ctx16[NTOK * EMB];                 // [B,T,E]
__device__ __half g_ffn16[NTOK * FFND];                // gelu(h @ W1^T)
__device__ float  g_x2   [NTOK * EMB];                 // fp32 residual stream
// fp16 weight copies
__device__ __half g_wqkv16[3 * EMB * EMB];             // wq|wk|wv rows
__device__ __half g_wo16[EMB * EMB];
__device__ __half g_w116[FFND * EMB];
__device__ __half g_w216[EMB * FFND];

// ---------------------------------------------------------------------------
// PTX helpers
// ---------------------------------------------------------------------------
__device__ __forceinline__ void cp16s(uint32_t dst, const void* src) {
    asm volatile("cp.async.ca.shared.global [%0], [%1], 16;" :: "r"(dst), "l"(src));
}
__device__ __forceinline__ void cp_commit() {
    asm volatile("cp.async.commit_group;" ::: "memory");
}
template<int N>
__device__ __forceinline__ void cp_wait() {
    asm volatile("cp.async.wait_group %0;" :: "n"(N) : "memory");
}
__device__ __forceinline__ uint32_t sw128(uint32_t o) {   // Swizzle<3,4,3>, 128B rows
    return o ^ ((o >> 3) & 0x70);
}
__device__ __forceinline__ uint32_t h2_u32(__half2 h) {
    return *reinterpret_cast<uint32_t*>(&h);
}
__device__ __forceinline__ void ldsm4(uint32_t* r, uint32_t addr) {
    asm volatile("ldmatrix.sync.aligned.m8n8.x4.shared.b16 {%0,%1,%2,%3}, [%4];"
        : "=r"(r[0]), "=r"(r[1]), "=r"(r[2]), "=r"(r[3]) : "r"(addr));
}
__device__ __forceinline__ void ldsm4t(uint32_t* r, uint32_t addr) {
    asm volatile("ldmatrix.sync.aligned.m8n8.x4.trans.shared.b16 {%0,%1,%2,%3}, [%4];"
        : "=r"(r[0]), "=r"(r[1]), "=r"(r[2]), "=r"(r[3]) : "r"(addr));
}
__device__ __forceinline__ void mma16816(float* d, const uint32_t* a, const uint32_t* b) {
    asm volatile(
        "mma.sync.aligned.m16n8k16.row.col.f32.f16.f16.f32 "
        "{%0,%1,%2,%3}, {%4,%5,%6,%7}, {%8,%9}, {%0,%1,%2,%3};"
        : "+f"(d[0]), "+f"(d[1]), "+f"(d[2]), "+f"(d[3])
        : "r"(a[0]), "r"(a[1]), "r"(a[2]), "r"(a[3]), "r"(b[0]), "r"(b[1]));
}

// ---------------------------------------------------------------------------
// Merged fp32 -> fp16 weight converter. blockIdx.y selects segment.
// ---------------------------------------------------------------------------
__global__ void f2h_all_k(const float* __restrict__ wq, const float* __restrict__ wk,
                          const float* __restrict__ wv, const float* __restrict__ wo,
                          const float* __restrict__ w1, const float* __restrict__ w2,
                          __half* __restrict__ dqkv, __half* __restrict__ dwo,
                          __half* __restrict__ dw1, __half* __restrict__ dw2) {
    const int seg = blockIdx.y;
    const int nblk = (seg < 4) ? (EMB * EMB / 1024) : (FFND * EMB / 1024);
    if (blockIdx.x >= nblk) return;
    const float* s;
    __half* d;
    switch (seg) {
        case 0: s = wq; d = dqkv;                 break;
        case 1: s = wk; d = dqkv + EMB * EMB;     break;
        case 2: s = wv; d = dqkv + 2 * EMB * EMB; break;
        case 3: s = wo; d = dwo;                  break;
        case 4: s = w1; d = dw1;                  break;
        default: s = w2; d = dw2;                 break;
    }
    int i = (blockIdx.x * 256 + threadIdx.x) * 4;
    float4 v = *(const float4*)(s + i);
    *(__half2*)(d + i)     = __floats2half2_rn(v.x, v.y);
    *(__half2*)(d + i + 2) = __floats2half2_rn(v.z, v.w);
}

// ---------------------------------------------------------------------------
// LayerNorm, warp-per-row (no block barriers): fp32 in, fp16 out.
// 256 threads = 8 warps = 8 rows per block; 1024 blocks.
// ---------------------------------------------------------------------------
__global__ void layernorm_k(const float* __restrict__ x, __half* __restrict__ o,
                            const float* __restrict__ sc, const float* __restrict__ sh) {
    const int lane = threadIdx.x & 31;
    const long row = (long)blockIdx.x * 8 + (threadIdx.x >> 5);
    const float4* p = (const float4*)(x + row * EMB);
    const float4* s4 = (const float4*)sc;
    const float4* b4 = (const float4*)sh;
    uint2* q = (uint2*)(o + row * EMB);

    float4 v[6];
    float sum = 0.0f, sq = 0.0f;
    #pragma unroll
    for (int j = 0; j < 6; j++) {
        v[j] = p[lane + 32 * j];
        sum += v[j].x + v[j].y + v[j].z + v[j].w;
        sq  += v[j].x * v[j].x + v[j].y * v[j].y + v[j].z * v[j].z + v[j].w * v[j].w;
    }
    #pragma unroll
    for (int ofs = 16; ofs; ofs >>= 1) {
        sum += __shfl_xor_sync(0xffffffffu, sum, ofs);
        sq  += __shfl_xor_sync(0xffffffffu, sq,  ofs);
    }
    float mean = sum * (1.0f / EMB);
    float var  = sq * (1.0f / EMB) - mean * mean;
    float rstd = rsqrtf(var + 1e-5f);

    #pragma unroll
    for (int j = 0; j < 6; j++) {
        float4 sv = s4[lane + 32 * j];
        float4 bv = b4[lane + 32 * j];
        __half2 h0 = __floats2half2_rn((v[j].x - mean) * rstd * sv.x + bv.x,
                                       (v[j].y - mean) * rstd * sv.y + bv.y);
        __half2 h1 = __floats2half2_rn((v[j].z - mean) * rstd * sv.z + bv.z,
                                       (v[j].w - mean) * rstd * sv.w + bv.w);
        q[lane + 32 * j] = make_uint2(h2_u32(h0), h2_u32(h1));
    }
}

// ---------------------------------------------------------------------------
// Flash attention: fused QK^T -> causal online softmax -> @V.
// 3-slot K/V ring (64 KB smem -> 2 CTAs/SM), prefetch distance 2,
// SINGLE barrier per KV tile: prefetch is issued AFTER the top barrier, so
// slot (it+2)%3 == (it-1)%3 is provably retired (all warps passed the barrier
// of it only after finishing compute on it-1). cp_wait<1> guarantees tile it
// complete (only the newest group, tile it+1, may still be in flight).
// Heavy q-tiles scheduled first.
// ---------------------------------------------------------------------------
__global__ void __launch_bounds__(256, 2)
flash_k(const __half* __restrict__ Qg, const __half* __restrict__ Kg,
        const __half* __restrict__ Vg, __half* __restrict__ O) {
    const int qt  = gridDim.x - 1 - blockIdx.x;     // heavy tiles first
    const int bh  = blockIdx.y;
    const int row0 = qt * 128;
    const int b = bh / NH, hh = bh % NH;

    extern __shared__ char smraw[];
    const uint32_t smQ = (uint32_t)__cvta_generic_to_shared(smraw);   // 16 KB
    const uint32_t smK = smQ + 128 * 128;                             // 3 x 8 KB
    const uint32_t smV = smK + 3 * 64 * 128;                          // 3 x 8 KB

    const int tid = threadIdx.x, lane = tid & 31, w = tid >> 5;
    const int g = lane >> 2, tig = lane & 3;
    const int aRow = (lane & 7) + ((lane >> 3) & 1) * 8, aChk = lane >> 4;
    const int bRow = (lane & 7) + (lane >> 4) * 8,       bChk = (lane >> 3) & 1;

    const __half* Qb = Qg + ((long)bh << 10) * HD;
    const __half* Kb = Kg + ((long)bh << 10) * HD;
    const __half* Vb = Vg + ((long)bh << 10) * HD;

    for (int i = tid; i < 128 * 8; i += 256) {
        int r = i >> 3, c = i & 7;
        cp16s(smQ + sw128(r * 128 + c * 16), Qb + (long)(row0 + r) * HD + c * 8);
    }
    cp_commit();

    const int nkv = 2 * qt + 2;
    auto load_kv = [&](int it, int s) {
        int kv0 = it * 64;
        #pragma unroll
        for (int i = 0; i < 2; i++) {
            int idx = tid + i * 256, r = idx >> 3, c = idx & 7;
            cp16s(smK + s * 8192 + sw128(r * 128 + c * 16), Kb + (long)(kv0 + r) * HD + c * 8);
        }
        #pragma unroll
        for (int i = 0; i < 2; i++) {
            int idx = tid + i * 256, r = idx >> 3, c = idx & 7;
            cp16s(smV + s * 8192 + sw128(r * 128 + c * 16), Vb + (long)(kv0 + r) * HD + c * 8);
        }
        cp_commit();
    };
    load_kv(0, 0);
    load_kv(1, 1);   // nkv >= 2 always

    cp_wait<2>();    // Q group complete (kv0, kv1 may be in flight)
    __syncthreads();
    uint32_t qf[4][4];
    #pragma unroll
    for (int kc = 0; kc < 4; kc++)
        ldsm4(qf[kc], smQ + sw128((w * 16 + aRow) * 128 + (kc * 2 + aChk) * 16));

    float oacc[8][4] = {};
    float m0 = -INFINITY, m1 = -INFINITY, l0 = 0.0f, l1 = 0.0f;
    const int r0g = row0 + w * 16 + g;
    const int r1g = r0g + 8;

    for (int it = 0; it < nkv; it++) {
        int s = it % 3;
        cp_wait<1>();        // tile it complete; tile it+1 may be in flight
        __syncthreads();     // visibility + slot (it-1) fully retired
        if (it + 2 < nkv) load_kv(it + 2, (it + 2) % 3); else cp_commit();

        uint32_t kS = smK + s * 8192, vS = smV + s * 8192;

        // ---- S = Q K^T ----
        float sacc[8][4] = {};
        #pragma unroll
        for (int kc = 0; kc < 4; kc++) {
            uint32_t bfr[8][2];
            #pragma unroll
            for (int j = 0; j < 4; j++) {
                uint32_t r4[4];
                ldsm4(r4, kS + sw128((j * 16 + bRow) * 128 + (kc * 2 + bChk) * 16));
                bfr[2*j][0] = r4[0]; bfr[2*j][1] = r4[1];
                bfr[2*j+1][0] = r4[2]; bfr[2*j+1][1] = r4[3];
            }
            #pragma unroll
            for (int ni = 0; ni < 8; ni++)
                mma16816(sacc[ni], qf[kc], bfr[ni]);
        }

        // ---- scale + causal mask + online softmax ----
        const int kv0 = it * 64;
        const bool needmask = (kv0 + 63) > (row0 + w * 16);
        float tm0 = -INFINITY, tm1 = -INFINITY;
        #pragma unroll
        for (int ni = 0; ni < 8; ni++) {
            float s0 = sacc[ni][0] * 0.125f, s1 = sacc[ni][1] * 0.125f;
            float s2 = sacc[ni][2] * 0.125f, s3 = sacc[ni][3] * 0.125f;
            if (needmask) {
                int col = kv0 + ni * 8 + tig * 2;
                if (col     > r0g) s0 = -1e30f;
                if (col + 1 > r0g) s1 = -1e30f;
                if (col     > r1g) s2 = -1e30f;
                if (col + 1 > r1g) s3 = -1e30f;
            }
            sacc[ni][0] = s0; sacc[ni][1] = s1; sacc[ni][2] = s2; sacc[ni][3] = s3;
            tm0 = fmaxf(tm0, fmaxf(s0, s1));
            tm1 = fmaxf(tm1, fmaxf(s2, s3));
        }
        #pragma unroll
        for (int o = 1; o <= 2; o <<= 1) {
            tm0 = fmaxf(tm0, __shfl_xor_sync(0xffffffffu, tm0, o));
            tm1 = fmaxf(tm1, __shfl_xor_sync(0xffffffffu, tm1, o));
        }
        float mn0 = fmaxf(m0, tm0), mn1 = fmaxf(m1, tm1);
        float f0 = __expf(m0 - mn0), f1 = __expf(m1 - mn1);
        m0 = mn0; m1 = mn1;

        uint32_t ph[8][2];
        float ls0 = 0.0f, ls1 = 0.0f;
        #pragma unroll
        for (int ni = 0; ni < 8; ni++) {
            float p0 = __expf(sacc[ni][0] - mn0), p1 = __expf(sacc[ni][1] - mn0);
            float p2 = __expf(sacc[ni][2] - mn1), p3 = __expf(sacc[ni][3] - mn1);
            ls0 += p0 + p1; ls1 += p2 + p3;
            ph[ni][0] = h2_u32(__floats2half2_rn(p0, p1));
            ph[ni][1] = h2_u32(__floats2half2_rn(p2, p3));
        }
        l0 = l0 * f0 + ls0;
        l1 = l1 * f1 + ls1;
        #pragma unroll
        for (int ni = 0; ni < 8; ni++) {
            oacc[ni][0] *= f0; oacc[ni][1] *= f0;
            oacc[ni][2] *= f1; oacc[ni][3] *= f1;
        }

        // ---- O += P @ V ----
        #pragma unroll
        for (int kc = 0; kc < 4; kc++) {
            uint32_t a[4] = { ph[2*kc][0], ph[2*kc][1], ph[2*kc+1][0], ph[2*kc+1][1] };
            uint32_t vb[8][2];
            #pragma unroll
            for (int j = 0; j < 4; j++) {
                uint32_t r4[4];
                ldsm4t(r4, vS + sw128((kc * 16 + aRow) * 128 + (2 * j + aChk) * 16));
                vb[2*j][0] = r4[0]; vb[2*j][1] = r4[1];
                vb[2*j+1][0] = r4[2]; vb[2*j+1][1] = r4[3];
            }
            #pragma unroll
            for (int nj = 0; nj < 8; nj++)
                mma16816(oacc[nj], a, vb[nj]);
        }
        // no bottom barrier: prefetch of slot (it-1) happens only after the
        // NEXT top barrier, which all warps reach after this tile's compute.
    }

    // ---- finalize ----
    #pragma unroll
    for (int o = 1; o <= 2; o <<= 1) {
        l0 += __shfl_xor_sync(0xffffffffu, l0, o);
        l1 += __shfl_xor_sync(0xffffffffu, l1, o);
    }
    float i0 = 1.0f / l0, i1 = 1.0f / l1;
    __half* Ob = O + ((long)(b << 10)) * EMB;
    #pragma unroll
    for (int ni = 0; ni < 8; ni++) {
        int col = hh * HD + ni * 8 + tig * 2;
        *(__half2*)&Ob[(long)r0g * EMB + col] = __floats2half2_rn(oacc[ni][0] * i0, oacc[ni][1] * i0);
        *(__half2*)&Ob[(long)r1g * EMB + col] = __floats2half2_rn(oacc[ni][2] * i1, oacc[ni][3] * i1);
    }
}

// ---------------------------------------------------------------------------
// fp16 tensor-core GEMM (m16n8k16, ldmatrix, SW128, 3-stage cp.async), NT:
//   C[m,n] = sum_k A[m,k] * B[n,k].  256 threads = 8 warps, 2 CTAs/SM.
// SINGLE barrier per K-tile (same argument as flash_k).
// ---------------------------------------------------------------------------
#define EPI_QKV3   0
#define EPI_RES    5
#define EPI_GELU   6

template<int BM, int BN, int WM, int WN, int EPI>
__global__ void __launch_bounds__(256, 2)
gemm_h(const __half* __restrict__ A, const __half* __restrict__ Bm,
       const float* __restrict__ R, void* __restrict__ Cv,
       int M, int N, int K) {
    constexpr int BK  = 64;
    constexpr int WTM = BM / WM, WTN = BN / WN;
    constexpr int MF  = WTM / 16, NF = WTN / 8;
    constexpr int A_STG = BM * BK * 2;
    constexpr int B_STG = BN * BK * 2;

    const int tid  = threadIdx.x;
    const int row0 = blockIdx.y * BM;
    const int col0 = blockIdx.x * BN;

    extern __shared__ char smraw[];
    const uint32_t smA = (uint32_t)__cvta_generic_to_shared(smraw);
    const uint32_t smB = smA + 3 * A_STG;

    auto load_tile = [&](int k0, int s) {
        uint32_t aB = smA + s * A_STG;
        #pragma unroll
        for (int i = 0; i < BM * 8 / 256; i++) {
            int idx = tid + i * 256, r = idx >> 3, c = idx & 7;
            cp16s(aB + sw128(r * 128 + c * 16), A + (long)(row0 + r) * K + k0 + c * 8);
        }
        uint32_t bB = smB + s * B_STG;
        #pragma unroll
        for (int i = 0; i < BN * 8 / 256; i++) {
            int idx = tid + i * 256, r = idx >> 3, c = idx & 7;
            cp16s(bB + sw128(r * 128 + c * 16), Bm + (long)(col0 + r) * K + k0 + c * 8);
        }
        cp_commit();
    };

    const int lane = tid & 31, w = tid >> 5;
    const int g = lane >> 2, tig = lane & 3;
    const int rw = (w % WM) * WTM, cw = (w / WM) * WTN;
    const int aRow = (lane & 7) + ((lane >> 3) & 1) * 8, aChk = lane >> 4;
    const int bRow = (lane & 7) + (lane >> 4) * 8,       bChk = (lane >> 3) & 1;

    float acc[MF][NF][4] = {};

    const int nt = K / BK;                // >= 12 for all our shapes
    load_tile(0, 0);
    load_tile(BK, 1);

    for (int it = 0; it < nt; it++) {
        int s = it % 3;
        cp_wait<1>();        // tile it complete; tile it+1 may be in flight
        __syncthreads();     // visibility + slot (it-1) fully retired
        if (it + 2 < nt) load_tile((it + 2) * BK, (it + 2) % 3); else cp_commit();
        uint32_t aS = smA + s * A_STG, bS = smB + s * B_STG;

        #pragma unroll
        for (int kk = 0; kk < BK; kk += 16) {
            uint32_t afr[MF][4];
            #pragma unroll
            for (int mi = 0; mi < MF; mi++)
                ldsm4(afr[mi], aS + sw128((rw + mi * 16 + aRow) * 128 + ((kk >> 3) + aChk) * 16));
            uint32_t bfr[NF][2];
            #pragma unroll
            for (int j = 0; j < NF / 2; j++) {
                uint32_t r4[4];
                ldsm4(r4, bS + sw128((cw + j * 16 + bRow) * 128 + ((kk >> 3) + bChk) * 16));
                bfr[2*j][0] = r4[0]; bfr[2*j][1] = r4[1];
                bfr[2*j+1][0] = r4[2]; bfr[2*j+1][1] = r4[3];
            }
            #pragma unroll
            for (int mi = 0; mi < MF; mi++)
                #pragma unroll
                for (int ni = 0; ni < NF; ni++)
                    mma16816(acc[mi][ni], afr[mi], bfr[ni]);
        }
        // no bottom barrier (see header comment)
    }

    // ---------------- epilogue ----------------
    #pragma unroll
    for (int mi = 0; mi < MF; mi++) {
        #pragma unroll
        for (int ni = 0; ni < NF; ni++) {
            int r_ = row0 + rw + mi * 16 + g;
            int c_ = col0 + cw + ni * 8 + tig * 2;
            float* a4 = acc[mi][ni];
            #pragma unroll
            for (int half = 0; half < 2; half++) {
                int rr = r_ + half * 8;
                float v0 = a4[half * 2 + 0];
                float v1 = a4[half * 2 + 1];

                if (EPI == EPI_QKV3) {
                    __half* Cp = (__half*)Cv;
                    int seg = c_ / EMB;
                    int cn  = c_ - seg * EMB;
                    int b = rr >> 10, t = rr & 1023;
                    int h = cn >> 6,  d = cn & 63;
                    long o = (long)seg * (NTOK * EMB)
                           + (((long)(b * NH + h) << 10) + t) * HD + d;
                    *(__half2*)&Cp[o] = __floats2half2_rn(v0, v1);
                } else if (EPI == EPI_RES) {
                    float* Cp = (float*)Cv;
                    long o = (long)rr * N + c_;
                    float2 rv = *(const float2*)&R[o];
                    *(float2*)&Cp[o] = make_float2(v0 + rv.x, v1 + rv.y);
                } else if (EPI == EPI_GELU) {
                    __half* Cp = (__half*)Cv;
                    // gelu_tanh(x) = x * sigmoid(2c(x + 0.044715 x^3)), exact identity
                    float y0 = 1.5957691216057308f * (v0 + 0.044715f * v0 * v0 * v0);
                    float y1 = 1.5957691216057308f * (v1 + 0.044715f * v1 * v1 * v1);
                    float g0 = v0 / (1.0f + __expf(-y0));
                    float g1 = v1 / (1.0f + __expf(-y1));
                    *(__half2*)&Cp[(long)rr * N + c_] = __floats2half2_rn(g0, g1);
                }
            }
        }
    }
}

// ---------------------------------------------------------------------------
// Launch
// ---------------------------------------------------------------------------
extern "C" void kernel_launch(void* const* d_in, const int* in_sizes, int n_in,
                              void* d_out, int out_size) {
    const float* x    = (const float*)d_in[0];
    const float* wq   = (const float*)d_in[1];
    const float* wk   = (const float*)d_in[2];
    const float* wv   = (const float*)d_in[3];
    const float* wo   = (const float*)d_in[4];
    const float* w1   = (const float*)d_in[5];
    const float* w2   = (const float*)d_in[6];
    const float* ln1s = (const float*)d_in[7];
    const float* ln1b = (const float*)d_in[8];
    const float* ln2s = (const float*)d_in[9];
    const float* ln2b = (const float*)d_in[10];
    float* out = (float*)d_out;

    __half *h16, *qkv16, *ctx16, *ffn16, *wqkv16, *wo16, *w116, *w216;
    float* x2;
    cudaGetSymbolAddress((void**)&h16,    g_h16);
    cudaGetSymbolAddress((void**)&qkv16,  g_qkv16);
    cudaGetSymbolAddress((void**)&ctx16,  g_ctx16);
    cudaGetSymbolAddress((void**)&ffn16,  g_ffn16);
    cudaGetSymbolAddress((void**)&x2,     g_x2);
    cudaGetSymbolAddress((void**)&wqkv16, g_wqkv16);
    cudaGetSymbolAddress((void**)&wo16,   g_wo16);
    cudaGetSymbolAddress((void**)&w116,   g_w116);
    cudaGetSymbolAddress((void**)&w216,   g_w216);

    __half* q16 = qkv16;
    __half* k16 = qkv16 + (long)NTOK * EMB;
    __half* v16 = qkv16 + 2L * NTOK * EMB;

    constexpr int SM_NT    = 3 * (128 * 64 + 128 * 64) * 2;    // 98304 B
    constexpr int SM_FLASH = 128 * 128 + 2 * 3 * 64 * 128 * 2; // 65536 B

    cudaFuncSetAttribute(gemm_h<128,128,2,4,EPI_QKV3>,
                         cudaFuncAttributeMaxDynamicSharedMemorySize, SM_NT);
    cudaFuncSetAttribute(gemm_h<128,128,2,4,EPI_RES>,
                         cudaFuncAttributeMaxDynamicSharedMemorySize, SM_NT);
    cudaFuncSetAttribute(gemm_h<128,128,2,4,EPI_GELU>,
                         cudaFuncAttributeMaxDynamicSharedMemorySize, SM_NT);
    cudaFuncSetAttribute(flash_k,
                         cudaFuncAttributeMaxDynamicSharedMemorySize, SM_FLASH);

    // 0) all weight fp32 -> fp16 conversions in one launch
    f2h_all_k<<<dim3(FFND * EMB / 1024, 6), 256>>>(
        wq, wk, wv, wo, w1, w2, wqkv16, wo16, w116, w216);

    // 1) LN1 (fp32 -> fp16), warp-per-row
    layernorm_k<<<NTOK / 8, 256>>>(x, h16, ln1s, ln1b);

    // 2) fused QKV projection : M=8192, N=2304, K=768 -> q|k|v [B,H,T,D]
    gemm_h<128,128,2,4,EPI_QKV3><<<dim3(3 * EMB / 128, NTOK / 128), 256, SM_NT>>>(
        h16, wqkv16, nullptr, qkv16, NTOK, 3 * EMB, EMB);

    // 3) flash attention -> ctx fp16 [B,T,E]
    flash_k<<<dim3(Tseq / 128, Bsz * NH), 256, SM_FLASH>>>(q16, k16, v16, ctx16);

    // 4) x2 = x + ctx @ Wo^T (fp32 residual) : M=8192, N=768, K=768
    gemm_h<128,128,2,4,EPI_RES><<<dim3(EMB / 128, NTOK / 128), 256, SM_NT>>>(
        ctx16, wo16, x, x2, NTOK, EMB, EMB);

    // 5) LN2 (fp32 -> fp16), warp-per-row
    layernorm_k<<<NTOK / 8, 256>>>(x2, h16, ln2s, ln2b);

    // 6) ffn = gelu(h @ W1^T) fp16 : M=8192, N=3072, K=768
    gemm_h<128,128,2,4,EPI_GELU><<<dim3(FFND / 128, NTOK / 128), 256, SM_NT>>>(
        h16, w116, nullptr, ffn16, NTOK, FFND, EMB);

    // 7) out = x2 + ffn @ W2^T (fp32 residual) : M=8192, N=768, K=3072
    gemm_h<128,128,2,4,EPI_RES><<<dim3(EMB / 128, NTOK / 128), 256, SM_NT>>>(
        ffn16, w216, x2, out, NTOK, EMB, FFND);
}

// round 15
// speedup vs baseline: 1.1811x; 1.0611x over previous
#include <cuda_runtime.h>
#include <cuda_fp16.h>
#include <math.h>
#include <stdint.h>

// ---------------------------------------------------------------------------
// Problem constants
// ---------------------------------------------------------------------------
#define Bsz   8
#define Tseq  1024
#define EMB   768
#define NH    12
#define HD    64
#define NTOK  (Bsz * Tseq)          // 8192
#define FFND  (4 * EMB)             // 3072

// ---------------------------------------------------------------------------
// Scratch (device globals — allocation-free)
// ---------------------------------------------------------------------------
__device__ __half g_h16  [NTOK * EMB];                 // LN output (fp16)
__device__ __half g_qkv16[3L * NTOK * EMB];            // q|k|v, each [B,H,T,D]
__device__ __half g_ctx16[NTOK * EMB];                 // [B,T,E]
__device__ __half g_ffn16[NTOK * FFND];                // gelu(h @ W1^T)
__device__ float  g_x2   [NTOK * EMB];                 // fp32 residual stream
// fp16 weight copies
__device__ __half g_wqkv16[3 * EMB * EMB];             // wq|wk|wv rows
__device__ __half g_wo16[EMB * EMB];
__device__ __half g_w116[FFND * EMB];
__device__ __half g_w216[EMB * FFND];

// ---------------------------------------------------------------------------
// PTX helpers
// ---------------------------------------------------------------------------
__device__ __forceinline__ void cp16s(uint32_t dst, const void* src) {
    asm volatile("cp.async.ca.shared.global [%0], [%1], 16;" :: "r"(dst), "l"(src));
}
__device__ __forceinline__ void cp_commit() {
    asm volatile("cp.async.commit_group;" ::: "memory");
}
template<int N>
__device__ __forceinline__ void cp_wait() {
    asm volatile("cp.async.wait_group %0;" :: "n"(N) : "memory");
}
__device__ __forceinline__ uint32_t sw128(uint32_t o) {   // Swizzle<3,4,3>, 128B rows
    return o ^ ((o >> 3) & 0x70);
}
__device__ __forceinline__ uint32_t h2_u32(__half2 h) {
    return *reinterpret_cast<uint32_t*>(&h);
}
__device__ __forceinline__ void ldsm4(uint32_t* r, uint32_t addr) {
    asm volatile("ldmatrix.sync.aligned.m8n8.x4.shared.b16 {%0,%1,%2,%3}, [%4];"
        : "=r"(r[0]), "=r"(r[1]), "=r"(r[2]), "=r"(r[3]) : "r"(addr));
}
__device__ __forceinline__ void ldsm4t(uint32_t* r, uint32_t addr) {
    asm volatile("ldmatrix.sync.aligned.m8n8.x4.trans.shared.b16 {%0,%1,%2,%3}, [%4];"
        : "=r"(r[0]), "=r"(r[1]), "=r"(r[2]), "=r"(r[3]) : "r"(addr));
}
__device__ __forceinline__ void mma16816(float* d, const uint32_t* a, const uint32_t* b) {
    asm volatile(
        "mma.sync.aligned.m16n8k16.row.col.f32.f16.f16.f32 "
        "{%0,%1,%2,%3}, {%4,%5,%6,%7}, {%8,%9}, {%0,%1,%2,%3};"
        : "+f"(d[0]), "+f"(d[1]), "+f"(d[2]), "+f"(d[3])
        : "r"(a[0]), "r"(a[1]), "r"(a[2]), "r"(a[3]), "r"(b[0]), "r"(b[1]));
}

// ---------------------------------------------------------------------------
// Merged fp32 -> fp16 weight converter. blockIdx.y selects segment.
// ---------------------------------------------------------------------------
__global__ void f2h_all_k(const float* __restrict__ wq, const float* __restrict__ wk,
                          const float* __restrict__ wv, const float* __restrict__ wo,
                          const float* __restrict__ w1, const float* __restrict__ w2,
                          __half* __restrict__ dqkv, __half* __restrict__ dwo,
                          __half* __restrict__ dw1, __half* __restrict__ dw2) {
    const int seg = blockIdx.y;
    const int nblk = (seg < 4) ? (EMB * EMB / 1024) : (FFND * EMB / 1024);
    if (blockIdx.x >= nblk) return;
    const float* s;
    __half* d;
    switch (seg) {
        case 0: s = wq; d = dqkv;                 break;
        case 1: s = wk; d = dqkv + EMB * EMB;     break;
        case 2: s = wv; d = dqkv + 2 * EMB * EMB; break;
        case 3: s = wo; d = dwo;                  break;
        case 4: s = w1; d = dw1;                  break;
        default: s = w2; d = dw2;                 break;
    }
    int i = (blockIdx.x * 256 + threadIdx.x) * 4;
    float4 v = *(const float4*)(s + i);
    *(__half2*)(d + i)     = __floats2half2_rn(v.x, v.y);
    *(__half2*)(d + i + 2) = __floats2half2_rn(v.z, v.w);
}

// ---------------------------------------------------------------------------
// LayerNorm, warp-per-row (no block barriers): fp32 in, fp16 out.
// 256 threads = 8 warps = 8 rows per block; 1024 blocks.
// ---------------------------------------------------------------------------
__global__ void layernorm_k(const float* __restrict__ x, __half* __restrict__ o,
                            const float* __restrict__ sc, const float* __restrict__ sh) {
    const int lane = threadIdx.x & 31;
    const long row = (long)blockIdx.x * 8 + (threadIdx.x >> 5);
    const float4* p = (const float4*)(x + row * EMB);
    const float4* s4 = (const float4*)sc;
    const float4* b4 = (const float4*)sh;
    uint2* q = (uint2*)(o + row * EMB);

    float4 v[6];
    float sum = 0.0f, sq = 0.0f;
    #pragma unroll
    for (int j = 0; j < 6; j++) {
        v[j] = p[lane + 32 * j];
        sum += v[j].x + v[j].y + v[j].z + v[j].w;
        sq  += v[j].x * v[j].x + v[j].y * v[j].y + v[j].z * v[j].z + v[j].w * v[j].w;
    }
    #pragma unroll
    for (int ofs = 16; ofs; ofs >>= 1) {
        sum += __shfl_xor_sync(0xffffffffu, sum, ofs);
        sq  += __shfl_xor_sync(0xffffffffu, sq,  ofs);
    }
    float mean = sum * (1.0f / EMB);
    float var  = sq * (1.0f / EMB) - mean * mean;
    float rstd = rsqrtf(var + 1e-5f);

    #pragma unroll
    for (int j = 0; j < 6; j++) {
        float4 sv = s4[lane + 32 * j];
        float4 bv = b4[lane + 32 * j];
        __half2 h0 = __floats2half2_rn((v[j].x - mean) * rstd * sv.x + bv.x,
                                       (v[j].y - mean) * rstd * sv.y + bv.y);
        __half2 h1 = __floats2half2_rn((v[j].z - mean) * rstd * sv.z + bv.z,
                                       (v[j].w - mean) * rstd * sv.w + bv.w);
        q[lane + 32 * j] = make_uint2(h2_u32(h0), h2_u32(h1));
    }
}

// ---------------------------------------------------------------------------
// Flash attention: fused QK^T -> causal online softmax -> @V.
// 3-slot K/V ring (64 KB smem -> 2 CTAs/SM), prefetch distance 2,
// single barrier per KV tile. Heavy q-tiles scheduled first.
// ---------------------------------------------------------------------------
__global__ void __launch_bounds__(256, 2)
flash_k(const __half* __restrict__ Qg, const __half* __restrict__ Kg,
        const __half* __restrict__ Vg, __half* __restrict__ O) {
    const int qt  = gridDim.x - 1 - blockIdx.x;     // heavy tiles first
    const int bh  = blockIdx.y;
    const int row0 = qt * 128;
    const int b = bh / NH, hh = bh % NH;

    extern __shared__ char smraw[];
    const uint32_t smQ = (uint32_t)__cvta_generic_to_shared(smraw);   // 16 KB
    const uint32_t smK = smQ + 128 * 128;                             // 3 x 8 KB
    const uint32_t smV = smK + 3 * 64 * 128;                          // 3 x 8 KB

    const int tid = threadIdx.x, lane = tid & 31, w = tid >> 5;
    const int g = lane >> 2, tig = lane & 3;
    const int aRow = (lane & 7) + ((lane >> 3) & 1) * 8, aChk = lane >> 4;
    const int bRow = (lane & 7) + (lane >> 4) * 8,       bChk = (lane >> 3) & 1;

    const __half* Qb = Qg + ((long)bh << 10) * HD;
    const __half* Kb = Kg + ((long)bh << 10) * HD;
    const __half* Vb = Vg + ((long)bh << 10) * HD;

    for (int i = tid; i < 128 * 8; i += 256) {
        int r = i >> 3, c = i & 7;
        cp16s(smQ + sw128(r * 128 + c * 16), Qb + (long)(row0 + r) * HD + c * 8);
    }
    cp_commit();

    const int nkv = 2 * qt + 2;
    auto load_kv = [&](int it, int s) {
        int kv0 = it * 64;
        #pragma unroll
        for (int i = 0; i < 2; i++) {
            int idx = tid + i * 256, r = idx >> 3, c = idx & 7;
            cp16s(smK + s * 8192 + sw128(r * 128 + c * 16), Kb + (long)(kv0 + r) * HD + c * 8);
        }
        #pragma unroll
        for (int i = 0; i < 2; i++) {
            int idx = tid + i * 256, r = idx >> 3, c = idx & 7;
            cp16s(smV + s * 8192 + sw128(r * 128 + c * 16), Vb + (long)(kv0 + r) * HD + c * 8);
        }
        cp_commit();
    };
    load_kv(0, 0);
    load_kv(1, 1);   // nkv >= 2 always

    cp_wait<2>();    // Q group complete (kv0, kv1 may be in flight)
    __syncthreads();
    uint32_t qf[4][4];
    #pragma unroll
    for (int kc = 0; kc < 4; kc++)
        ldsm4(qf[kc], smQ + sw128((w * 16 + aRow) * 128 + (kc * 2 + aChk) * 16));

    float oacc[8][4] = {};
    float m0 = -INFINITY, m1 = -INFINITY, l0 = 0.0f, l1 = 0.0f;
    const int r0g = row0 + w * 16 + g;
    const int r1g = r0g + 8;

    for (int it = 0; it < nkv; it++) {
        int s = it % 3;
        cp_wait<1>();        // tile it complete; tile it+1 may be in flight
        __syncthreads();     // visibility + slot (it-1) fully retired
        if (it + 2 < nkv) load_kv(it + 2, (it + 2) % 3); else cp_commit();

        uint32_t kS = smK + s * 8192, vS = smV + s * 8192;

        // ---- S = Q K^T ----
        float sacc[8][4] = {};
        #pragma unroll
        for (int kc = 0; kc < 4; kc++) {
            uint32_t bfr[8][2];
            #pragma unroll
            for (int j = 0; j < 4; j++) {
                uint32_t r4[4];
                ldsm4(r4, kS + sw128((j * 16 + bRow) * 128 + (kc * 2 + bChk) * 16));
                bfr[2*j][0] = r4[0]; bfr[2*j][1] = r4[1];
                bfr[2*j+1][0] = r4[2]; bfr[2*j+1][1] = r4[3];
            }
            #pragma unroll
            for (int ni = 0; ni < 8; ni++)
                mma16816(sacc[ni], qf[kc], bfr[ni]);
        }

        // ---- scale + causal mask + online softmax ----
        const int kv0 = it * 64;
        const bool needmask = (kv0 + 63) > (row0 + w * 16);
        float tm0 = -INFINITY, tm1 = -INFINITY;
        #pragma unroll
        for (int ni = 0; ni < 8; ni++) {
            float s0 = sacc[ni][0] * 0.125f, s1 = sacc[ni][1] * 0.125f;
            float s2 = sacc[ni][2] * 0.125f, s3 = sacc[ni][3] * 0.125f;
            if (needmask) {
                int col = kv0 + ni * 8 + tig * 2;
                if (col     > r0g) s0 = -1e30f;
                if (col + 1 > r0g) s1 = -1e30f;
                if (col     > r1g) s2 = -1e30f;
                if (col + 1 > r1g) s3 = -1e30f;
            }
            sacc[ni][0] = s0; sacc[ni][1] = s1; sacc[ni][2] = s2; sacc[ni][3] = s3;
            tm0 = fmaxf(tm0, fmaxf(s0, s1));
            tm1 = fmaxf(tm1, fmaxf(s2, s3));
        }
        #pragma unroll
        for (int o = 1; o <= 2; o <<= 1) {
            tm0 = fmaxf(tm0, __shfl_xor_sync(0xffffffffu, tm0, o));
            tm1 = fmaxf(tm1, __shfl_xor_sync(0xffffffffu, tm1, o));
        }
        float mn0 = fmaxf(m0, tm0), mn1 = fmaxf(m1, tm1);
        float f0 = __expf(m0 - mn0), f1 = __expf(m1 - mn1);
        m0 = mn0; m1 = mn1;

        uint32_t ph[8][2];
        float ls0 = 0.0f, ls1 = 0.0f;
        #pragma unroll
        for (int ni = 0; ni < 8; ni++) {
            float p0 = __expf(sacc[ni][0] - mn0), p1 = __expf(sacc[ni][1] - mn0);
            float p2 = __expf(sacc[ni][2] - mn1), p3 = __expf(sacc[ni][3] - mn1);
            ls0 += p0 + p1; ls1 += p2 + p3;
            ph[ni][0] = h2_u32(__floats2half2_rn(p0, p1));
            ph[ni][1] = h2_u32(__floats2half2_rn(p2, p3));
        }
        l0 = l0 * f0 + ls0;
        l1 = l1 * f1 + ls1;
        #pragma unroll
        for (int ni = 0; ni < 8; ni++) {
            oacc[ni][0] *= f0; oacc[ni][1] *= f0;
            oacc[ni][2] *= f1; oacc[ni][3] *= f1;
        }

        // ---- O += P @ V ----
        #pragma unroll
        for (int kc = 0; kc < 4; kc++) {
            uint32_t a[4] = { ph[2*kc][0], ph[2*kc][1], ph[2*kc+1][0], ph[2*kc+1][1] };
            uint32_t vb[8][2];
            #pragma unroll
            for (int j = 0; j < 4; j++) {
                uint32_t r4[4];
                ldsm4t(r4, vS + sw128((kc * 16 + aRow) * 128 + (2 * j + aChk) * 16));
                vb[2*j][0] = r4[0]; vb[2*j][1] = r4[1];
                vb[2*j+1][0] = r4[2]; vb[2*j+1][1] = r4[3];
            }
            #pragma unroll
            for (int nj = 0; nj < 8; nj++)
                mma16816(oacc[nj], a, vb[nj]);
        }
        // no bottom barrier (single-barrier ring argument)
    }

    // ---- finalize ----
    #pragma unroll
    for (int o = 1; o <= 2; o <<= 1) {
        l0 += __shfl_xor_sync(0xffffffffu, l0, o);
        l1 += __shfl_xor_sync(0xffffffffu, l1, o);
    }
    float i0 = 1.0f / l0, i1 = 1.0f / l1;
    __half* Ob = O + ((long)(b << 10)) * EMB;
    #pragma unroll
    for (int ni = 0; ni < 8; ni++) {
        int col = hh * HD + ni * 8 + tig * 2;
        *(__half2*)&Ob[(long)r0g * EMB + col] = __floats2half2_rn(oacc[ni][0] * i0, oacc[ni][1] * i0);
        *(__half2*)&Ob[(long)r1g * EMB + col] = __floats2half2_rn(oacc[ni][2] * i1, oacc[ni][3] * i1);
    }
}

// ---------------------------------------------------------------------------
// fp16 tensor-core GEMM (m16n8k16, ldmatrix, SW128), NT:
//   C[m,n] = sum_k A[m,k] * B[n,k].  256 threads = 8 warps.
// 2-stage double buffer, 64 KB smem -> 2 CTAs/SM (smem budget is ~144-159KB,
// NOT 228: 3x32KB stages forced 1 CTA/SM). Single barrier per K-tile:
// prefetch of tile it+1 goes to slot (it+1)&1 = slot consumed at it-1,
// provably retired by this iteration's barrier. cp_wait<0> at top waits the
// consumed tile (nothing newer is outstanding at that point).
// ---------------------------------------------------------------------------
#define EPI_QKV3   0
#define EPI_RES    5
#define EPI_GELU   6

template<int BM, int BN, int WM, int WN, int EPI>
__global__ void __launch_bounds__(256, 2)
gemm_h(const __half* __restrict__ A, const __half* __restrict__ Bm,
       const float* __restrict__ R, void* __restrict__ Cv,
       int M, int N, int K) {
    constexpr int BK  = 64;
    constexpr int WTM = BM / WM, WTN = BN / WN;
    constexpr int MF  = WTM / 16, NF = WTN / 8;
    constexpr int A_STG = BM * BK * 2;
    constexpr int B_STG = BN * BK * 2;

    const int tid  = threadIdx.x;
    const int row0 = blockIdx.y * BM;
    const int col0 = blockIdx.x * BN;

    extern __shared__ char smraw[];
    const uint32_t smA = (uint32_t)__cvta_generic_to_shared(smraw);
    const uint32_t smB = smA + 2 * A_STG;

    auto load_tile = [&](int k0, int s) {
        uint32_t aB = smA + s * A_STG;
        #pragma unroll
        for (int i = 0; i < BM * 8 / 256; i++) {
            int idx = tid + i * 256, r = idx >> 3, c = idx & 7;
            cp16s(aB + sw128(r * 128 + c * 16), A + (long)(row0 + r) * K + k0 + c * 8);
        }
        uint32_t bB = smB + s * B_STG;
        #pragma unroll
        for (int i = 0; i < BN * 8 / 256; i++) {
            int idx = tid + i * 256, r = idx >> 3, c = idx & 7;
            cp16s(bB + sw128(r * 128 + c * 16), Bm + (long)(col0 + r) * K + k0 + c * 8);
        }
        cp_commit();
    };

    const int lane = tid & 31, w = tid >> 5;
    const int g = lane >> 2, tig = lane & 3;
    const int rw = (w % WM) * WTM, cw = (w / WM) * WTN;
    const int aRow = (lane & 7) + ((lane >> 3) & 1) * 8, aChk = lane >> 4;
    const int bRow = (lane & 7) + (lane >> 4) * 8,       bChk = (lane >> 3) & 1;

    float acc[MF][NF][4] = {};

    const int nt = K / BK;                // >= 12 for all our shapes
    load_tile(0, 0);

    for (int it = 0; it < nt; it++) {
        int s = it & 1;
        cp_wait<0>();        // tile it complete (nothing newer outstanding)
        __syncthreads();     // visibility + slot (it-1) fully retired
        if (it + 1 < nt) load_tile((it + 1) * BK, (it + 1) & 1);
        uint32_t aS = smA + s * A_STG, bS = smB + s * B_STG;

        #pragma unroll
        for (int kk = 0; kk < BK; kk += 16) {
            uint32_t afr[MF][4];
            #pragma unroll
            for (int mi = 0; mi < MF; mi++)
                ldsm4(afr[mi], aS + sw128((rw + mi * 16 + aRow) * 128 + ((kk >> 3) + aChk) * 16));
            uint32_t bfr[NF][2];
            #pragma unroll
            for (int j = 0; j < NF / 2; j++) {
                uint32_t r4[4];
                ldsm4(r4, bS + sw128((cw + j * 16 + bRow) * 128 + ((kk >> 3) + bChk) * 16));
                bfr[2*j][0] = r4[0]; bfr[2*j][1] = r4[1];
                bfr[2*j+1][0] = r4[2]; bfr[2*j+1][1] = r4[3];
            }
            #pragma unroll
            for (int mi = 0; mi < MF; mi++)
                #pragma unroll
                for (int ni = 0; ni < NF; ni++)
                    mma16816(acc[mi][ni], afr[mi], bfr[ni]);
        }
        // no bottom barrier (see header comment)
    }

    // ---------------- epilogue ----------------
    #pragma unroll
    for (int mi = 0; mi < MF; mi++) {
        #pragma unroll
        for (int ni = 0; ni < NF; ni++) {
            int r_ = row0 + rw + mi * 16 + g;
            int c_ = col0 + cw + ni * 8 + tig * 2;
            float* a4 = acc[mi][ni];
            #pragma unroll
            for (int half = 0; half < 2; half++) {
                int rr = r_ + half * 8;
                float v0 = a4[half * 2 + 0];
                float v1 = a4[half * 2 + 1];

                if (EPI == EPI_QKV3) {
                    __half* Cp = (__half*)Cv;
                    int seg = c_ / EMB;
                    int cn  = c_ - seg * EMB;
                    int b = rr >> 10, t = rr & 1023;
                    int h = cn >> 6,  d = cn & 63;
                    long o = (long)seg * (NTOK * EMB)
                           + (((long)(b * NH + h) << 10) + t) * HD + d;
                    *(__half2*)&Cp[o] = __floats2half2_rn(v0, v1);
                } else if (EPI == EPI_RES) {
                    float* Cp = (float*)Cv;
                    long o = (long)rr * N + c_;
                    float2 rv = *(const float2*)&R[o];
                    *(float2*)&Cp[o] = make_float2(v0 + rv.x, v1 + rv.y);
                } else if (EPI == EPI_GELU) {
                    __half* Cp = (__half*)Cv;
                    // gelu_tanh(x) = x * sigmoid(2c(x + 0.044715 x^3)), exact identity
                    float y0 = 1.5957691216057308f * (v0 + 0.044715f * v0 * v0 * v0);
                    float y1 = 1.5957691216057308f * (v1 + 0.044715f * v1 * v1 * v1);
                    float g0 = v0 / (1.0f + __expf(-y0));
                    float g1 = v1 / (1.0f + __expf(-y1));
                    *(__half2*)&Cp[(long)rr * N + c_] = __floats2half2_rn(g0, g1);
                }
            }
        }
    }
}

// ---------------------------------------------------------------------------
// Launch
// ---------------------------------------------------------------------------
extern "C" void kernel_launch(void* const* d_in, const int* in_sizes, int n_in,
                              void* d_out, int out_size) {
    const float* x    = (const float*)d_in[0];
    const float* wq   = (const float*)d_in[1];
    const float* wk   = (const float*)d_in[2];
    const float* wv   = (const float*)d_in[3];
    const float* wo   = (const float*)d_in[4];
    const float* w1   = (const float*)d_in[5];
    const float* w2   = (const float*)d_in[6];
    const float* ln1s = (const float*)d_in[7];
    const float* ln1b = (const float*)d_in[8];
    const float* ln2s = (const float*)d_in[9];
    const float* ln2b = (const float*)d_in[10];
    float* out = (float*)d_out;

    __half *h16, *qkv16, *ctx16, *ffn16, *wqkv16, *wo16, *w116, *w216;
    float* x2;
    cudaGetSymbolAddress((void**)&h16,    g_h16);
    cudaGetSymbolAddress((void**)&qkv16,  g_qkv16);
    cudaGetSymbolAddress((void**)&ctx16,  g_ctx16);
    cudaGetSymbolAddress((void**)&ffn16,  g_ffn16);
    cudaGetSymbolAddress((void**)&x2,     g_x2);
    cudaGetSymbolAddress((void**)&wqkv16, g_wqkv16);
    cudaGetSymbolAddress((void**)&wo16,   g_wo16);
    cudaGetSymbolAddress((void**)&w116,   g_w116);
    cudaGetSymbolAddress((void**)&w216,   g_w216);

    __half* q16 = qkv16;
    __half* k16 = qkv16 + (long)NTOK * EMB;
    __half* v16 = qkv16 + 2L * NTOK * EMB;

    constexpr int SM_NT    = 2 * (128 * 64 + 128 * 64) * 2;    // 65536 B -> 2 CTAs/SM
    constexpr int SM_FLASH = 128 * 128 + 2 * 3 * 64 * 128 * 2; // 65536 B

    cudaFuncSetAttribute(gemm_h<128,128,2,4,EPI_QKV3>,
                         cudaFuncAttributeMaxDynamicSharedMemorySize, SM_NT);
    cudaFuncSetAttribute(gemm_h<128,128,2,4,EPI_RES>,
                         cudaFuncAttributeMaxDynamicSharedMemorySize, SM_NT);
    cudaFuncSetAttribute(gemm_h<128,128,2,4,EPI_GELU>,
                         cudaFuncAttributeMaxDynamicSharedMemorySize, SM_NT);
    cudaFuncSetAttribute(flash_k,
                         cudaFuncAttributeMaxDynamicSharedMemorySize, SM_FLASH);

    // 0) all weight fp32 -> fp16 conversions in one launch
    f2h_all_k<<<dim3(FFND * EMB / 1024, 6), 256>>>(
        wq, wk, wv, wo, w1, w2, wqkv16, wo16, w116, w216);

    // 1) LN1 (fp32 -> fp16), warp-per-row
    layernorm_k<<<NTOK / 8, 256>>>(x, h16, ln1s, ln1b);

    // 2) fused QKV projection : M=8192, N=2304, K=768 -> q|k|v [B,H,T,D]
    gemm_h<128,128,2,4,EPI_QKV3><<<dim3(3 * EMB / 128, NTOK / 128), 256, SM_NT>>>(
        h16, wqkv16, nullptr, qkv16, NTOK, 3 * EMB, EMB);

    // 3) flash attention -> ctx fp16 [B,T,E]
    flash_k<<<dim3(Tseq / 128, Bsz * NH), 256, SM_FLASH>>>(q16, k16, v16, ctx16);

    // 4) x2 = x + ctx @ Wo^T (fp32 residual) : M=8192, N=768, K=768
    gemm_h<128,128,2,4,EPI_RES><<<dim3(EMB / 128, NTOK / 128), 256, SM_NT>>>(
        ctx16, wo16, x, x2, NTOK, EMB, EMB);

    // 5) LN2 (fp32 -> fp16), warp-per-row
    layernorm_k<<<NTOK / 8, 256>>>(x2, h16, ln2s, ln2b);

    // 6) ffn = gelu(h @ W1^T) fp16 : M=8192, N=3072, K=768
    gemm_h<128,128,2,4,EPI_GELU><<<dim3(FFND / 128, NTOK / 128), 256, SM_NT>>>(
        h16, w116, nullptr, ffn16, NTOK, FFND, EMB);

    // 7) out = x2 + ffn @ W2^T (fp32 residual) : M=8192, N=768, K=3072
    gemm_h<128,128,2,4,EPI_RES><<<dim3(EMB / 128, NTOK / 128), 256, SM_NT>>>(
        ffn16, w216, x2, out, NTOK, EMB, FFND);
}

// round 16
// speedup vs baseline: 1.2902x; 1.0924x over previous
#include <cuda_runtime.h>
#include <cuda_fp16.h>
#include <math.h>
#include <stdint.h>

// ---------------------------------------------------------------------------
// Problem constants
// ---------------------------------------------------------------------------
#define Bsz   8
#define Tseq  1024
#define EMB   768
#define NH    12
#define HD    64
#define NTOK  (Bsz * Tseq)          // 8192
#define FFND  (4 * EMB)             // 3072

// ---------------------------------------------------------------------------
// Scratch (device globals — allocation-free)
// ---------------------------------------------------------------------------
__device__ __half g_h16  [NTOK * EMB];                 // LN output (fp16)
__device__ __half g_qkv16[3L * NTOK * EMB];            // q|k|v, each [B,H,T,D]
__device__ __half g_ctx16[NTOK * EMB];                 // [B,T,E]
__device__ __half g_ffn16[NTOK * FFND];                // gelu(h @ W1^T)
__device__ float  g_x2   [NTOK * EMB];                 // fp32 residual stream
// fp16 weight copies
__device__ __half g_wqkv16[3 * EMB * EMB];             // wq|wk|wv rows
__device__ __half g_wo16[EMB * EMB];
__device__ __half g_w116[FFND * EMB];
__device__ __half g_w216[EMB * FFND];

// ---------------------------------------------------------------------------
// PTX helpers
// ---------------------------------------------------------------------------
__device__ __forceinline__ void cp16s(uint32_t dst, const void* src) {
    // .cg: bypass L1 (staged data is consumed once from smem; keep L1 for ldsm)
    asm volatile("cp.async.cg.shared.global [%0], [%1], 16;" :: "r"(dst), "l"(src));
}
__device__ __forceinline__ void cp_commit() {
    asm volatile("cp.async.commit_group;" ::: "memory");
}
template<int N>
__device__ __forceinline__ void cp_wait() {
    asm volatile("cp.async.wait_group %0;" :: "n"(N) : "memory");
}
__device__ __forceinline__ uint32_t sw128(uint32_t o) {   // Swizzle<3,4,3>, 128B rows
    return o ^ ((o >> 3) & 0x70);
}
__device__ __forceinline__ uint32_t h2_u32(__half2 h) {
    return *reinterpret_cast<uint32_t*>(&h);
}
__device__ __forceinline__ void ldsm4(uint32_t* r, uint32_t addr) {
    asm volatile("ldmatrix.sync.aligned.m8n8.x4.shared.b16 {%0,%1,%2,%3}, [%4];"
        : "=r"(r[0]), "=r"(r[1]), "=r"(r[2]), "=r"(r[3]) : "r"(addr));
}
__device__ __forceinline__ void ldsm4t(uint32_t* r, uint32_t addr) {
    asm volatile("ldmatrix.sync.aligned.m8n8.x4.trans.shared.b16 {%0,%1,%2,%3}, [%4];"
        : "=r"(r[0]), "=r"(r[1]), "=r"(r[2]), "=r"(r[3]) : "r"(addr));
}
__device__ __forceinline__ void mma16816(float* d, const uint32_t* a, const uint32_t* b) {
    asm volatile(
        "mma.sync.aligned.m16n8k16.row.col.f32.f16.f16.f32 "
        "{%0,%1,%2,%3}, {%4,%5,%6,%7}, {%8,%9}, {%0,%1,%2,%3};"
        : "+f"(d[0]), "+f"(d[1]), "+f"(d[2]), "+f"(d[3])
        : "r"(a[0]), "r"(a[1]), "r"(a[2]), "r"(a[3]), "r"(b[0]), "r"(b[1]));
}

// ---------------------------------------------------------------------------
// Merged fp32 -> fp16 weight converter. blockIdx.y selects segment.
// ---------------------------------------------------------------------------
__global__ void f2h_all_k(const float* __restrict__ wq, const float* __restrict__ wk,
                          const float* __restrict__ wv, const float* __restrict__ wo,
                          const float* __restrict__ w1, const float* __restrict__ w2,
                          __half* __restrict__ dqkv, __half* __restrict__ dwo,
                          __half* __restrict__ dw1, __half* __restrict__ dw2) {
    const int seg = blockIdx.y;
    const int nblk = (seg < 4) ? (EMB * EMB / 1024) : (FFND * EMB / 1024);
    if (blockIdx.x >= nblk) return;
    const float* s;
    __half* d;
    switch (seg) {
        case 0: s = wq; d = dqkv;                 break;
        case 1: s = wk; d = dqkv + EMB * EMB;     break;
        case 2: s = wv; d = dqkv + 2 * EMB * EMB; break;
        case 3: s = wo; d = dwo;                  break;
        case 4: s = w1; d = dw1;                  break;
        default: s = w2; d = dw2;                 break;
    }
    int i = (blockIdx.x * 256 + threadIdx.x) * 4;
    float4 v = *(const float4*)(s + i);
    *(__half2*)(d + i)     = __floats2half2_rn(v.x, v.y);
    *(__half2*)(d + i + 2) = __floats2half2_rn(v.z, v.w);
}

// ---------------------------------------------------------------------------
// LayerNorm, warp-per-row (no block barriers): fp32 in, fp16 out.
// 256 threads = 8 warps = 8 rows per block; 1024 blocks.
// ---------------------------------------------------------------------------
__global__ void layernorm_k(const float* __restrict__ x, __half* __restrict__ o,
                            const float* __restrict__ sc, const float* __restrict__ sh) {
    const int lane = threadIdx.x & 31;
    const long row = (long)blockIdx.x * 8 + (threadIdx.x >> 5);
    const float4* p = (const float4*)(x + row * EMB);
    const float4* s4 = (const float4*)sc;
    const float4* b4 = (const float4*)sh;
    uint2* q = (uint2*)(o + row * EMB);

    float4 v[6];
    float sum = 0.0f, sq = 0.0f;
    #pragma unroll
    for (int j = 0; j < 6; j++) {
        v[j] = p[lane + 32 * j];
        sum += v[j].x + v[j].y + v[j].z + v[j].w;
        sq  += v[j].x * v[j].x + v[j].y * v[j].y + v[j].z * v[j].z + v[j].w * v[j].w;
    }
    #pragma unroll
    for (int ofs = 16; ofs; ofs >>= 1) {
        sum += __shfl_xor_sync(0xffffffffu, sum, ofs);
        sq  += __shfl_xor_sync(0xffffffffu, sq,  ofs);
    }
    float mean = sum * (1.0f / EMB);
    float var  = sq * (1.0f / EMB) - mean * mean;
    float rstd = rsqrtf(var + 1e-5f);

    #pragma unroll
    for (int j = 0; j < 6; j++) {
        float4 sv = s4[lane + 32 * j];
        float4 bv = b4[lane + 32 * j];
        __half2 h0 = __floats2half2_rn((v[j].x - mean) * rstd * sv.x + bv.x,
                                       (v[j].y - mean) * rstd * sv.y + bv.y);
        __half2 h1 = __floats2half2_rn((v[j].z - mean) * rstd * sv.z + bv.z,
                                       (v[j].w - mean) * rstd * sv.w + bv.w);
        q[lane + 32 * j] = make_uint2(h2_u32(h0), h2_u32(h1));
    }
}

// ---------------------------------------------------------------------------
// Flash attention: fused QK^T -> causal online softmax (exp2 domain) -> @V.
// Scores scaled by 0.125*log2(e) so all exponentials are single EX2 ops.
// 3-slot K/V ring (64 KB smem -> 2 CTAs/SM), prefetch distance 2,
// single barrier per KV tile. Heavy q-tiles scheduled first.
// ---------------------------------------------------------------------------
#define SCALE_LOG2E 0.18033688011112042f   // 0.125 * log2(e)

__global__ void __launch_bounds__(256, 2)
flash_k(const __half* __restrict__ Qg, const __half* __restrict__ Kg,
        const __half* __restrict__ Vg, __half* __restrict__ O) {
    const int qt  = gridDim.x - 1 - blockIdx.x;     // heavy tiles first
    const int bh  = blockIdx.y;
    const int row0 = qt * 128;
    const int b = bh / NH, hh = bh % NH;

    extern __shared__ char smraw[];
    const uint32_t smQ = (uint32_t)__cvta_generic_to_shared(smraw);   // 16 KB
    const uint32_t smK = smQ + 128 * 128;                             // 3 x 8 KB
    const uint32_t smV = smK + 3 * 64 * 128;                          // 3 x 8 KB

    const int tid = threadIdx.x, lane = tid & 31, w = tid >> 5;
    const int g = lane >> 2, tig = lane & 3;
    const int aRow = (lane & 7) + ((lane >> 3) & 1) * 8, aChk = lane >> 4;
    const int bRow = (lane & 7) + (lane >> 4) * 8,       bChk = (lane >> 3) & 1;

    const __half* Qb = Qg + ((long)bh << 10) * HD;
    const __half* Kb = Kg + ((long)bh << 10) * HD;
    const __half* Vb = Vg + ((long)bh << 10) * HD;

    for (int i = tid; i < 128 * 8; i += 256) {
        int r = i >> 3, c = i & 7;
        cp16s(smQ + sw128(r * 128 + c * 16), Qb + (long)(row0 + r) * HD + c * 8);
    }
    cp_commit();

    const int nkv = 2 * qt + 2;
    auto load_kv = [&](int it, int s) {
        int kv0 = it * 64;
        #pragma unroll
        for (int i = 0; i < 2; i++) {
            int idx = tid + i * 256, r = idx >> 3, c = idx & 7;
            cp16s(smK + s * 8192 + sw128(r * 128 + c * 16), Kb + (long)(kv0 + r) * HD + c * 8);
        }
        #pragma unroll
        for (int i = 0; i < 2; i++) {
            int idx = tid + i * 256, r = idx >> 3, c = idx & 7;
            cp16s(smV + s * 8192 + sw128(r * 128 + c * 16), Vb + (long)(kv0 + r) * HD + c * 8);
        }
        cp_commit();
    };
    load_kv(0, 0);
    load_kv(1, 1);   // nkv >= 2 always

    cp_wait<2>();    // Q group complete (kv0, kv1 may be in flight)
    __syncthreads();
    uint32_t qf[4][4];
    #pragma unroll
    for (int kc = 0; kc < 4; kc++)
        ldsm4(qf[kc], smQ + sw128((w * 16 + aRow) * 128 + (kc * 2 + aChk) * 16));

    float oacc[8][4] = {};
    float m0 = -INFINITY, m1 = -INFINITY, l0 = 0.0f, l1 = 0.0f;
    const int r0g = row0 + w * 16 + g;
    const int r1g = r0g + 8;

    for (int it = 0; it < nkv; it++) {
        int s = it % 3;
        cp_wait<1>();        // tile it complete; tile it+1 may be in flight
        __syncthreads();     // visibility + slot (it-1) fully retired
        if (it + 2 < nkv) load_kv(it + 2, (it + 2) % 3); else cp_commit();

        uint32_t kS = smK + s * 8192, vS = smV + s * 8192;

        // ---- S = Q K^T ----
        float sacc[8][4] = {};
        #pragma unroll
        for (int kc = 0; kc < 4; kc++) {
            uint32_t bfr[8][2];
            #pragma unroll
            for (int j = 0; j < 4; j++) {
                uint32_t r4[4];
                ldsm4(r4, kS + sw128((j * 16 + bRow) * 128 + (kc * 2 + bChk) * 16));
                bfr[2*j][0] = r4[0]; bfr[2*j][1] = r4[1];
                bfr[2*j+1][0] = r4[2]; bfr[2*j+1][1] = r4[3];
            }
            #pragma unroll
            for (int ni = 0; ni < 8; ni++)
                mma16816(sacc[ni], qf[kc], bfr[ni]);
        }

        // ---- scale (into log2 domain) + causal mask + online softmax ----
        const int kv0 = it * 64;
        const bool needmask = (kv0 + 63) > (row0 + w * 16);
        float tm0 = -INFINITY, tm1 = -INFINITY;
        #pragma unroll
        for (int ni = 0; ni < 8; ni++) {
            float s0 = sacc[ni][0] * SCALE_LOG2E, s1 = sacc[ni][1] * SCALE_LOG2E;
            float s2 = sacc[ni][2] * SCALE_LOG2E, s3 = sacc[ni][3] * SCALE_LOG2E;
            if (needmask) {
                int col = kv0 + ni * 8 + tig * 2;
                if (col     > r0g) s0 = -1e30f;
                if (col + 1 > r0g) s1 = -1e30f;
                if (col     > r1g) s2 = -1e30f;
                if (col + 1 > r1g) s3 = -1e30f;
            }
            sacc[ni][0] = s0; sacc[ni][1] = s1; sacc[ni][2] = s2; sacc[ni][3] = s3;
            tm0 = fmaxf(tm0, fmaxf(s0, s1));
            tm1 = fmaxf(tm1, fmaxf(s2, s3));
        }
        #pragma unroll
        for (int o = 1; o <= 2; o <<= 1) {
            tm0 = fmaxf(tm0, __shfl_xor_sync(0xffffffffu, tm0, o));
            tm1 = fmaxf(tm1, __shfl_xor_sync(0xffffffffu, tm1, o));
        }
        float mn0 = fmaxf(m0, tm0), mn1 = fmaxf(m1, tm1);
        float f0 = exp2f(m0 - mn0), f1 = exp2f(m1 - mn1);
        m0 = mn0; m1 = mn1;

        uint32_t ph[8][2];
        float ls0 = 0.0f, ls1 = 0.0f;
        #pragma unroll
        for (int ni = 0; ni < 8; ni++) {
            float p0 = exp2f(sacc[ni][0] - mn0), p1 = exp2f(sacc[ni][1] - mn0);
            float p2 = exp2f(sacc[ni][2] - mn1), p3 = exp2f(sacc[ni][3] - mn1);
            ls0 += p0 + p1; ls1 += p2 + p3;
            ph[ni][0] = h2_u32(__floats2half2_rn(p0, p1));
            ph[ni][1] = h2_u32(__floats2half2_rn(p2, p3));
        }
        l0 = l0 * f0 + ls0;
        l1 = l1 * f1 + ls1;
        #pragma unroll
        for (int ni = 0; ni < 8; ni++) {
            oacc[ni][0] *= f0; oacc[ni][1] *= f0;
            oacc[ni][2] *= f1; oacc[ni][3] *= f1;
        }

        // ---- O += P @ V ----
        #pragma unroll
        for (int kc = 0; kc < 4; kc++) {
            uint32_t a[4] = { ph[2*kc][0], ph[2*kc][1], ph[2*kc+1][0], ph[2*kc+1][1] };
            uint32_t vb[8][2];
            #pragma unroll
            for (int j = 0; j < 4; j++) {
                uint32_t r4[4];
                ldsm4t(r4, vS + sw128((kc * 16 + aRow) * 128 + (2 * j + aChk) * 16));
                vb[2*j][0] = r4[0]; vb[2*j][1] = r4[1];
                vb[2*j+1][0] = r4[2]; vb[2*j+1][1] = r4[3];
            }
            #pragma unroll
            for (int nj = 0; nj < 8; nj++)
                mma16816(oacc[nj], a, vb[nj]);
        }
        // no bottom barrier (single-barrier ring argument)
    }

    // ---- finalize ----
    #pragma unroll
    for (int o = 1; o <= 2; o <<= 1) {
        l0 += __shfl_xor_sync(0xffffffffu, l0, o);
        l1 += __shfl_xor_sync(0xffffffffu, l1, o);
    }
    float i0 = 1.0f / l0, i1 = 1.0f / l1;
    __half* Ob = O + ((long)(b << 10)) * EMB;
    #pragma unroll
    for (int ni = 0; ni < 8; ni++) {
        int col = hh * HD + ni * 8 + tig * 2;
        *(__half2*)&Ob[(long)r0g * EMB + col] = __floats2half2_rn(oacc[ni][0] * i0, oacc[ni][1] * i0);
        *(__half2*)&Ob[(long)r1g * EMB + col] = __floats2half2_rn(oacc[ni][2] * i1, oacc[ni][3] * i1);
    }
}

// ---------------------------------------------------------------------------
// fp16 tensor-core GEMM (m16n8k16, ldmatrix, SW128), NT:
//   C[m,n] = sum_k A[m,k] * B[n,k].  256 threads = 8 warps.
// 2-stage double buffer, 64 KB smem -> 2 CTAs/SM. Single barrier per K-tile.
// ---------------------------------------------------------------------------
#define EPI_QKV3   0
#define EPI_RES    5
#define EPI_GELU   6

template<int BM, int BN, int WM, int WN, int EPI>
__global__ void __launch_bounds__(256, 2)
gemm_h(const __half* __restrict__ A, const __half* __restrict__ Bm,
       const float* __restrict__ R, void* __restrict__ Cv,
       int M, int N, int K) {
    constexpr int BK  = 64;
    constexpr int WTM = BM / WM, WTN = BN / WN;
    constexpr int MF  = WTM / 16, NF = WTN / 8;
    constexpr int A_STG = BM * BK * 2;
    constexpr int B_STG = BN * BK * 2;

    const int tid  = threadIdx.x;
    const int row0 = blockIdx.y * BM;
    const int col0 = blockIdx.x * BN;

    extern __shared__ char smraw[];
    const uint32_t smA = (uint32_t)__cvta_generic_to_shared(smraw);
    const uint32_t smB = smA + 2 * A_STG;

    auto load_tile = [&](int k0, int s) {
        uint32_t aB = smA + s * A_STG;
        #pragma unroll
        for (int i = 0; i < BM * 8 / 256; i++) {
            int idx = tid + i * 256, r = idx >> 3, c = idx & 7;
            cp16s(aB + sw128(r * 128 + c * 16), A + (long)(row0 + r) * K + k0 + c * 8);
        }
        uint32_t bB = smB + s * B_STG;
        #pragma unroll
        for (int i = 0; i < BN * 8 / 256; i++) {
            int idx = tid + i * 256, r = idx >> 3, c = idx & 7;
            cp16s(bB + sw128(r * 128 + c * 16), Bm + (long)(col0 + r) * K + k0 + c * 8);
        }
        cp_commit();
    };

    const int lane = tid & 31, w = tid >> 5;
    const int g = lane >> 2, tig = lane & 3;
    const int rw = (w % WM) * WTM, cw = (w / WM) * WTN;
    const int aRow = (lane & 7) + ((lane >> 3) & 1) * 8, aChk = lane >> 4;
    const int bRow = (lane & 7) + (lane >> 4) * 8,       bChk = (lane >> 3) & 1;

    float acc[MF][NF][4] = {};

    const int nt = K / BK;                // >= 12 for all our shapes
    load_tile(0, 0);

    for (int it = 0; it < nt; it++) {
        int s = it & 1;
        cp_wait<0>();        // tile it complete (nothing newer outstanding)
        __syncthreads();     // visibility + slot (it-1) fully retired
        if (it + 1 < nt) load_tile((it + 1) * BK, (it + 1) & 1);
        uint32_t aS = smA + s * A_STG, bS = smB + s * B_STG;

        #pragma unroll
        for (int kk = 0; kk < BK; kk += 16) {
            uint32_t afr[MF][4];
            #pragma unroll
            for (int mi = 0; mi < MF; mi++)
                ldsm4(afr[mi], aS + sw128((rw + mi * 16 + aRow) * 128 + ((kk >> 3) + aChk) * 16));
            uint32_t bfr[NF][2];
            #pragma unroll
            for (int j = 0; j < NF / 2; j++) {
                uint32_t r4[4];
                ldsm4(r4, bS + sw128((cw + j * 16 + bRow) * 128 + ((kk >> 3) + bChk) * 16));
                bfr[2*j][0] = r4[0]; bfr[2*j][1] = r4[1];
                bfr[2*j+1][0] = r4[2]; bfr[2*j+1][1] = r4[3];
            }
            #pragma unroll
            for (int mi = 0; mi < MF; mi++)
                #pragma unroll
                for (int ni = 0; ni < NF; ni++)
                    mma16816(acc[mi][ni], afr[mi], bfr[ni]);
        }
        // no bottom barrier
    }

    // ---------------- epilogue ----------------
    #pragma unroll
    for (int mi = 0; mi < MF; mi++) {
        #pragma unroll
        for (int ni = 0; ni < NF; ni++) {
            int r_ = row0 + rw + mi * 16 + g;
            int c_ = col0 + cw + ni * 8 + tig * 2;
            float* a4 = acc[mi][ni];
            #pragma unroll
            for (int half = 0; half < 2; half++) {
                int rr = r_ + half * 8;
                float v0 = a4[half * 2 + 0];
                float v1 = a4[half * 2 + 1];

                if (EPI == EPI_QKV3) {
                    __half* Cp = (__half*)Cv;
                    int seg = c_ / EMB;
                    int cn  = c_ - seg * EMB;
                    int b = rr >> 10, t = rr & 1023;
                    int h = cn >> 6,  d = cn & 63;
                    long o = (long)seg * (NTOK * EMB)
                           + (((long)(b * NH + h) << 10) + t) * HD + d;
                    *(__half2*)&Cp[o] = __floats2half2_rn(v0, v1);
                } else if (EPI == EPI_RES) {
                    float* Cp = (float*)Cv;
                    long o = (long)rr * N + c_;
                    float2 rv = *(const float2*)&R[o];
                    *(float2*)&Cp[o] = make_float2(v0 + rv.x, v1 + rv.y);
                } else if (EPI == EPI_GELU) {
                    __half* Cp = (__half*)Cv;
                    // gelu_tanh(x) = x * sigmoid(2c(x + 0.044715 x^3)), exact identity
                    float y0 = 1.5957691216057308f * (v0 + 0.044715f * v0 * v0 * v0);
                    float y1 = 1.5957691216057308f * (v1 + 0.044715f * v1 * v1 * v1);
                    float g0 = v0 / (1.0f + __expf(-y0));
                    float g1 = v1 / (1.0f + __expf(-y1));
                    *(__half2*)&Cp[(long)rr * N + c_] = __floats2half2_rn(g0, g1);
                }
            }
        }
    }
}

// ---------------------------------------------------------------------------
// Launch
// ---------------------------------------------------------------------------
extern "C" void kernel_launch(void* const* d_in, const int* in_sizes, int n_in,
                              void* d_out, int out_size) {
    const float* x    = (const float*)d_in[0];
    const float* wq   = (const float*)d_in[1];
    const float* wk   = (const float*)d_in[2];
    const float* wv   = (const float*)d_in[3];
    const float* wo   = (const float*)d_in[4];
    const float* w1   = (const float*)d_in[5];
    const float* w2   = (const float*)d_in[6];
    const float* ln1s = (const float*)d_in[7];
    const float* ln1b = (const float*)d_in[8];
    const float* ln2s = (const float*)d_in[9];
    const float* ln2b = (const float*)d_in[10];
    float* out = (float*)d_out;

    __half *h16, *qkv16, *ctx16, *ffn16, *wqkv16, *wo16, *w116, *w216;
    float* x2;
    cudaGetSymbolAddress((void**)&h16,    g_h16);
    cudaGetSymbolAddress((void**)&qkv16,  g_qkv16);
    cudaGetSymbolAddress((void**)&ctx16,  g_ctx16);
    cudaGetSymbolAddress((void**)&ffn16,  g_ffn16);
    cudaGetSymbolAddress((void**)&x2,     g_x2);
    cudaGetSymbolAddress((void**)&wqkv16, g_wqkv16);
    cudaGetSymbolAddress((void**)&wo16,   g_wo16);
    cudaGetSymbolAddress((void**)&w116,   g_w116);
    cudaGetSymbolAddress((void**)&w216,   g_w216);

    __half* q16 = qkv16;
    __half* k16 = qkv16 + (long)NTOK * EMB;
    __half* v16 = qkv16 + 2L * NTOK * EMB;

    constexpr int SM_NT    = 2 * (128 * 64 + 128 * 64) * 2;    // 65536 B -> 2 CTAs/SM
    constexpr int SM_FLASH = 128 * 128 + 2 * 3 * 64 * 128 * 2; // 65536 B

    cudaFuncSetAttribute(gemm_h<128,128,2,4,EPI_QKV3>,
                         cudaFuncAttributeMaxDynamicSharedMemorySize, SM_NT);
    cudaFuncSetAttribute(gemm_h<128,128,2,4,EPI_RES>,
                         cudaFuncAttributeMaxDynamicSharedMemorySize, SM_NT);
    cudaFuncSetAttribute(gemm_h<128,128,2,4,EPI_GELU>,
                         cudaFuncAttributeMaxDynamicSharedMemorySize, SM_NT);
    cudaFuncSetAttribute(flash_k,
                         cudaFuncAttributeMaxDynamicSharedMemorySize, SM_FLASH);

    // 0) all weight fp32 -> fp16 conversions in one launch
    f2h_all_k<<<dim3(FFND * EMB / 1024, 6), 256>>>(
        wq, wk, wv, wo, w1, w2, wqkv16, wo16, w116, w216);

    // 1) LN1 (fp32 -> fp16), warp-per-row
    layernorm_k<<<NTOK / 8, 256>>>(x, h16, ln1s, ln1b);

    // 2) fused QKV projection : M=8192, N=2304, K=768 -> q|k|v [B,H,T,D]
    gemm_h<128,128,2,4,EPI_QKV3><<<dim3(3 * EMB / 128, NTOK / 128), 256, SM_NT>>>(
        h16, wqkv16, nullptr, qkv16, NTOK, 3 * EMB, EMB);

    // 3) flash attention -> ctx fp16 [B,T,E]
    flash_k<<<dim3(Tseq / 128, Bsz * NH), 256, SM_FLASH>>>(q16, k16, v16, ctx16);

    // 4) x2 = x + ctx @ Wo^T (fp32 residual) : M=8192, N=768, K=768
    gemm_h<128,128,2,4,EPI_RES><<<dim3(EMB / 128, NTOK / 128), 256, SM_NT>>>(
        ctx16, wo16, x, x2, NTOK, EMB, EMB);

    // 5) LN2 (fp32 -> fp16), warp-per-row
    layernorm_k<<<NTOK / 8, 256>>>(x2, h16, ln2s, ln2b);

    // 6) ffn = gelu(h @ W1^T) fp16 : M=8192, N=3072, K=768
    gemm_h<128,128,2,4,EPI_GELU><<<dim3(FFND / 128, NTOK / 128), 256, SM_NT>>>(
        h16, w116, nullptr, ffn16, NTOK, FFND, EMB);

    // 7) out = x2 + ffn @ W2^T (fp32 residual) : M=8192, N=768, K=3072
    gemm_h<128,128,2,4,EPI_RES><<<dim3(EMB / 128, NTOK / 128), 256, SM_NT>>>(
        ffn16, w216, x2, out, NTOK, EMB, FFND);
}

// round 17
// speedup vs baseline: 1.2924x; 1.0017x over previous
#include <cuda_runtime.h>
#include <cuda_fp16.h>
#include <math.h>
#include <stdint.h>

// ---------------------------------------------------------------------------
// Problem constants
// ---------------------------------------------------------------------------
#define Bsz   8
#define Tseq  1024
#define EMB   768
#define NH    12
#define HD    64
#define NTOK  (Bsz * Tseq)          // 8192
#define FFND  (4 * EMB)             // 3072

// ---------------------------------------------------------------------------
// Scratch (device globals — allocation-free)
// ---------------------------------------------------------------------------
__device__ __half g_h16  [NTOK * EMB];                 // LN output (fp16)
__device__ __half g_qkv16[3L * NTOK * EMB];            // q|k|v, each [B,H,T,D]
__device__ __half g_ctx16[NTOK * EMB];                 // [B,T,E]
__device__ __half g_ffn16[NTOK * FFND];                // gelu(h @ W1^T)
__device__ float  g_x2   [NTOK * EMB];                 // fp32 residual stream
// fp16 weight copies
__device__ __half g_wqkv16[3 * EMB * EMB];             // wq|wk|wv rows
__device__ __half g_wo16[EMB * EMB];
__device__ __half g_w116[FFND * EMB];
__device__ __half g_w216[EMB * FFND];

// ---------------------------------------------------------------------------
// PTX helpers
// ---------------------------------------------------------------------------
__device__ __forceinline__ void cp16s(uint32_t dst, const void* src) {
    // .cg: bypass L1 (staged data is consumed once from smem; keep L1 for ldsm)
    asm volatile("cp.async.cg.shared.global [%0], [%1], 16;" :: "r"(dst), "l"(src));
}
__device__ __forceinline__ void cp_commit() {
    asm volatile("cp.async.commit_group;" ::: "memory");
}
template<int N>
__device__ __forceinline__ void cp_wait() {
    asm volatile("cp.async.wait_group %0;" :: "n"(N) : "memory");
}
__device__ __forceinline__ uint32_t sw128(uint32_t o) {   // Swizzle<3,4,3>, 128B rows
    return o ^ ((o >> 3) & 0x70);
}
__device__ __forceinline__ uint32_t h2_u32(__half2 h) {
    return *reinterpret_cast<uint32_t*>(&h);
}
__device__ __forceinline__ float ex2f(float x) {          // single MUFU.EX2
    float r;
    asm("ex2.approx.ftz.f32 %0, %1;" : "=f"(r) : "f"(x));
    return r;
}
__device__ __forceinline__ void ldsm4(uint32_t* r, uint32_t addr) {
    asm volatile("ldmatrix.sync.aligned.m8n8.x4.shared.b16 {%0,%1,%2,%3}, [%4];"
        : "=r"(r[0]), "=r"(r[1]), "=r"(r[2]), "=r"(r[3]) : "r"(addr));
}
__device__ __forceinline__ void ldsm4t(uint32_t* r, uint32_t addr) {
    asm volatile("ldmatrix.sync.aligned.m8n8.x4.trans.shared.b16 {%0,%1,%2,%3}, [%4];"
        : "=r"(r[0]), "=r"(r[1]), "=r"(r[2]), "=r"(r[3]) : "r"(addr));
}
__device__ __forceinline__ void mma16816(float* d, const uint32_t* a, const uint32_t* b) {
    asm volatile(
        "mma.sync.aligned.m16n8k16.row.col.f32.f16.f16.f32 "
        "{%0,%1,%2,%3}, {%4,%5,%6,%7}, {%8,%9}, {%0,%1,%2,%3};"
        : "+f"(d[0]), "+f"(d[1]), "+f"(d[2]), "+f"(d[3])
        : "r"(a[0]), "r"(a[1]), "r"(a[2]), "r"(a[3]), "r"(b[0]), "r"(b[1]));
}

// ---------------------------------------------------------------------------
// Merged fp32 -> fp16 weight converter. blockIdx.y selects segment.
// ---------------------------------------------------------------------------
__global__ void f2h_all_k(const float* __restrict__ wq, const float* __restrict__ wk,
                          const float* __restrict__ wv, const float* __restrict__ wo,
                          const float* __restrict__ w1, const float* __restrict__ w2,
                          __half* __restrict__ dqkv, __half* __restrict__ dwo,
                          __half* __restrict__ dw1, __half* __restrict__ dw2) {
    const int seg = blockIdx.y;
    const int nblk = (seg < 4) ? (EMB * EMB / 1024) : (FFND * EMB / 1024);
    if (blockIdx.x >= nblk) return;
    const float* s;
    __half* d;
    switch (seg) {
        case 0: s = wq; d = dqkv;                 break;
        case 1: s = wk; d = dqkv + EMB * EMB;     break;
        case 2: s = wv; d = dqkv + 2 * EMB * EMB; break;
        case 3: s = wo; d = dwo;                  break;
        case 4: s = w1; d = dw1;                  break;
        default: s = w2; d = dw2;                 break;
    }
    int i = (blockIdx.x * 256 + threadIdx.x) * 4;
    float4 v = *(const float4*)(s + i);
    *(__half2*)(d + i)     = __floats2half2_rn(v.x, v.y);
    *(__half2*)(d + i + 2) = __floats2half2_rn(v.z, v.w);
}

// ---------------------------------------------------------------------------
// LayerNorm, warp-per-row (no block barriers): fp32 in, fp16 out.
// 256 threads = 8 warps = 8 rows per block; 1024 blocks.
// ---------------------------------------------------------------------------
__global__ void layernorm_k(const float* __restrict__ x, __half* __restrict__ o,
                            const float* __restrict__ sc, const float* __restrict__ sh) {
    const int lane = threadIdx.x & 31;
    const long row = (long)blockIdx.x * 8 + (threadIdx.x >> 5);
    const float4* p = (const float4*)(x + row * EMB);
    const float4* s4 = (const float4*)sc;
    const float4* b4 = (const float4*)sh;
    uint2* q = (uint2*)(o + row * EMB);

    float4 v[6];
    float sum = 0.0f, sq = 0.0f;
    #pragma unroll
    for (int j = 0; j < 6; j++) {
        v[j] = p[lane + 32 * j];
        sum += v[j].x + v[j].y + v[j].z + v[j].w;
        sq  += v[j].x * v[j].x + v[j].y * v[j].y + v[j].z * v[j].z + v[j].w * v[j].w;
    }
    #pragma unroll
    for (int ofs = 16; ofs; ofs >>= 1) {
        sum += __shfl_xor_sync(0xffffffffu, sum, ofs);
        sq  += __shfl_xor_sync(0xffffffffu, sq,  ofs);
    }
    float mean = sum * (1.0f / EMB);
    float var  = sq * (1.0f / EMB) - mean * mean;
    float rstd = rsqrtf(var + 1e-5f);

    #pragma unroll
    for (int j = 0; j < 6; j++) {
        float4 sv = s4[lane + 32 * j];
        float4 bv = b4[lane + 32 * j];
        __half2 h0 = __floats2half2_rn((v[j].x - mean) * rstd * sv.x + bv.x,
                                       (v[j].y - mean) * rstd * sv.y + bv.y);
        __half2 h1 = __floats2half2_rn((v[j].z - mean) * rstd * sv.z + bv.z,
                                       (v[j].w - mean) * rstd * sv.w + bv.w);
        q[lane + 32 * j] = make_uint2(h2_u32(h0), h2_u32(h1));
    }
}

// ---------------------------------------------------------------------------
// Flash attention: fused QK^T -> causal online softmax (exp2 domain) -> @V.
// Probability exponentials via h2exp2 (one MUFU op per 2 values, fp16 result
// feeds the PV MMA directly); rescale factors via single-op ex2.approx.f32.
// 3-slot K/V ring (64 KB smem -> 2 CTAs/SM), prefetch distance 2,
// single barrier per KV tile. Heavy q-tiles scheduled first.
// ---------------------------------------------------------------------------
#define SCALE_LOG2E 0.18033688011112042f   // 0.125 * log2(e)

__global__ void __launch_bounds__(256, 2)
flash_k(const __half* __restrict__ Qg, const __half* __restrict__ Kg,
        const __half* __restrict__ Vg, __half* __restrict__ O) {
    const int qt  = gridDim.x - 1 - blockIdx.x;     // heavy tiles first
    const int bh  = blockIdx.y;
    const int row0 = qt * 128;
    const int b = bh / NH, hh = bh % NH;

    extern __shared__ char smraw[];
    const uint32_t smQ = (uint32_t)__cvta_generic_to_shared(smraw);   // 16 KB
    const uint32_t smK = smQ + 128 * 128;                             // 3 x 8 KB
    const uint32_t smV = smK + 3 * 64 * 128;                          // 3 x 8 KB

    const int tid = threadIdx.x, lane = tid & 31, w = tid >> 5;
    const int g = lane >> 2, tig = lane & 3;
    const int aRow = (lane & 7) + ((lane >> 3) & 1) * 8, aChk = lane >> 4;
    const int bRow = (lane & 7) + (lane >> 4) * 8,       bChk = (lane >> 3) & 1;

    const __half* Qb = Qg + ((long)bh << 10) * HD;
    const __half* Kb = Kg + ((long)bh << 10) * HD;
    const __half* Vb = Vg + ((long)bh << 10) * HD;

    for (int i = tid; i < 128 * 8; i += 256) {
        int r = i >> 3, c = i & 7;
        cp16s(smQ + sw128(r * 128 + c * 16), Qb + (long)(row0 + r) * HD + c * 8);
    }
    cp_commit();

    const int nkv = 2 * qt + 2;
    auto load_kv = [&](int it, int s) {
        int kv0 = it * 64;
        #pragma unroll
        for (int i = 0; i < 2; i++) {
            int idx = tid + i * 256, r = idx >> 3, c = idx & 7;
            cp16s(smK + s * 8192 + sw128(r * 128 + c * 16), Kb + (long)(kv0 + r) * HD + c * 8);
        }
        #pragma unroll
        for (int i = 0; i < 2; i++) {
            int idx = tid + i * 256, r = idx >> 3, c = idx & 7;
            cp16s(smV + s * 8192 + sw128(r * 128 + c * 16), Vb + (long)(kv0 + r) * HD + c * 8);
        }
        cp_commit();
    };
    load_kv(0, 0);
    load_kv(1, 1);   // nkv >= 2 always

    cp_wait<2>();    // Q group complete (kv0, kv1 may be in flight)
    __syncthreads();
    uint32_t qf[4][4];
    #pragma unroll
    for (int kc = 0; kc < 4; kc++)
        ldsm4(qf[kc], smQ + sw128((w * 16 + aRow) * 128 + (kc * 2 + aChk) * 16));

    float oacc[8][4] = {};
    float m0 = -INFINITY, m1 = -INFINITY, l0 = 0.0f, l1 = 0.0f;
    const int r0g = row0 + w * 16 + g;
    const int r1g = r0g + 8;

    for (int it = 0; it < nkv; it++) {
        int s = it % 3;
        cp_wait<1>();        // tile it complete; tile it+1 may be in flight
        __syncthreads();     // visibility + slot (it-1) fully retired
        if (it + 2 < nkv) load_kv(it + 2, (it + 2) % 3); else cp_commit();

        uint32_t kS = smK + s * 8192, vS = smV + s * 8192;

        // ---- S = Q K^T ----
        float sacc[8][4] = {};
        #pragma unroll
        for (int kc = 0; kc < 4; kc++) {
            uint32_t bfr[8][2];
            #pragma unroll
            for (int j = 0; j < 4; j++) {
                uint32_t r4[4];
                ldsm4(r4, kS + sw128((j * 16 + bRow) * 128 + (kc * 2 + bChk) * 16));
                bfr[2*j][0] = r4[0]; bfr[2*j][1] = r4[1];
                bfr[2*j+1][0] = r4[2]; bfr[2*j+1][1] = r4[3];
            }
            #pragma unroll
            for (int ni = 0; ni < 8; ni++)
                mma16816(sacc[ni], qf[kc], bfr[ni]);
        }

        // ---- scale (into log2 domain) + causal mask + online softmax ----
        const int kv0 = it * 64;
        const bool needmask = (kv0 + 63) > (row0 + w * 16);
        float tm0 = -INFINITY, tm1 = -INFINITY;
        #pragma unroll
        for (int ni = 0; ni < 8; ni++) {
            float s0 = sacc[ni][0] * SCALE_LOG2E, s1 = sacc[ni][1] * SCALE_LOG2E;
            float s2 = sacc[ni][2] * SCALE_LOG2E, s3 = sacc[ni][3] * SCALE_LOG2E;
            if (needmask) {
                int col = kv0 + ni * 8 + tig * 2;
                if (col     > r0g) s0 = -1e30f;
                if (col + 1 > r0g) s1 = -1e30f;
                if (col     > r1g) s2 = -1e30f;
                if (col + 1 > r1g) s3 = -1e30f;
            }
            sacc[ni][0] = s0; sacc[ni][1] = s1; sacc[ni][2] = s2; sacc[ni][3] = s3;
            tm0 = fmaxf(tm0, fmaxf(s0, s1));
            tm1 = fmaxf(tm1, fmaxf(s2, s3));
        }
        #pragma unroll
        for (int o = 1; o <= 2; o <<= 1) {
            tm0 = fmaxf(tm0, __shfl_xor_sync(0xffffffffu, tm0, o));
            tm1 = fmaxf(tm1, __shfl_xor_sync(0xffffffffu, tm1, o));
        }
        float mn0 = fmaxf(m0, tm0), mn1 = fmaxf(m1, tm1);
        float f0 = ex2f(m0 - mn0), f1 = ex2f(m1 - mn1);
        m0 = mn0; m1 = mn1;

        // p = exp2(s - m) computed directly in fp16 pairs (h2exp2: 1 MUFU / 2 vals);
        // fp16 is the PV-MMA operand precision anyway.
        uint32_t ph[8][2];
        float ls0 = 0.0f, ls1 = 0.0f;
        #pragma unroll
        for (int ni = 0; ni < 8; ni++) {
            __half2 a0 = __floats2half2_rn(sacc[ni][0] - mn0, sacc[ni][1] - mn0);
            __half2 a1 = __floats2half2_rn(sacc[ni][2] - mn1, sacc[ni][3] - mn1);
            __half2 p0 = h2exp2(a0);
            __half2 p1 = h2exp2(a1);
            ph[ni][0] = h2_u32(p0);
            ph[ni][1] = h2_u32(p1);
            float2 q0 = __half22float2(p0);
            float2 q1 = __half22float2(p1);
            ls0 += q0.x + q0.y;
            ls1 += q1.x + q1.y;
        }
        l0 = l0 * f0 + ls0;
        l1 = l1 * f1 + ls1;
        #pragma unroll
        for (int ni = 0; ni < 8; ni++) {
            oacc[ni][0] *= f0; oacc[ni][1] *= f0;
            oacc[ni][2] *= f1; oacc[ni][3] *= f1;
        }

        // ---- O += P @ V ----
        #pragma unroll
        for (int kc = 0; kc < 4; kc++) {
            uint32_t a[4] = { ph[2*kc][0], ph[2*kc][1], ph[2*kc+1][0], ph[2*kc+1][1] };
            uint32_t vb[8][2];
            #pragma unroll
            for (int j = 0; j < 4; j++) {
                uint32_t r4[4];
                ldsm4t(r4, vS + sw128((kc * 16 + aRow) * 128 + (2 * j + aChk) * 16));
                vb[2*j][0] = r4[0]; vb[2*j][1] = r4[1];
                vb[2*j+1][0] = r4[2]; vb[2*j+1][1] = r4[3];
            }
            #pragma unroll
            for (int nj = 0; nj < 8; nj++)
                mma16816(oacc[nj], a, vb[nj]);
        }
        // no bottom barrier (single-barrier ring argument)
    }

    // ---- finalize ----
    #pragma unroll
    for (int o = 1; o <= 2; o <<= 1) {
        l0 += __shfl_xor_sync(0xffffffffu, l0, o);
        l1 += __shfl_xor_sync(0xffffffffu, l1, o);
    }
    float i0 = 1.0f / l0, i1 = 1.0f / l1;
    __half* Ob = O + ((long)(b << 10)) * EMB;
    #pragma unroll
    for (int ni = 0; ni < 8; ni++) {
        int col = hh * HD + ni * 8 + tig * 2;
        *(__half2*)&Ob[(long)r0g * EMB + col] = __floats2half2_rn(oacc[ni][0] * i0, oacc[ni][1] * i0);
        *(__half2*)&Ob[(long)r1g * EMB + col] = __floats2half2_rn(oacc[ni][2] * i1, oacc[ni][3] * i1);
    }
}

// ---------------------------------------------------------------------------
// fp16 tensor-core GEMM (m16n8k16, ldmatrix, SW128), NT:
//   C[m,n] = sum_k A[m,k] * B[n,k].  256 threads = 8 warps.
// 2-stage double buffer, 64 KB smem -> 2 CTAs/SM. Single barrier per K-tile.
// ---------------------------------------------------------------------------
#define EPI_QKV3   0
#define EPI_RES    5
#define EPI_GELU   6

template<int BM, int BN, int WM, int WN, int EPI>
__global__ void __launch_bounds__(256, 2)
gemm_h(const __half* __restrict__ A, const __half* __restrict__ Bm,
       const float* __restrict__ R, void* __restrict__ Cv,
       int M, int N, int K) {
    constexpr int BK  = 64;
    constexpr int WTM = BM / WM, WTN = BN / WN;
    constexpr int MF  = WTM / 16, NF = WTN / 8;
    constexpr int A_STG = BM * BK * 2;
    constexpr int B_STG = BN * BK * 2;

    const int tid  = threadIdx.x;
    const int row0 = blockIdx.y * BM;
    const int col0 = blockIdx.x * BN;

    extern __shared__ char smraw[];
    const uint32_t smA = (uint32_t)__cvta_generic_to_shared(smraw);
    const uint32_t smB = smA + 2 * A_STG;

    auto load_tile = [&](int k0, int s) {
        uint32_t aB = smA + s * A_STG;
        #pragma unroll
        for (int i = 0; i < BM * 8 / 256; i++) {
            int idx = tid + i * 256, r = idx >> 3, c = idx & 7;
            cp16s(aB + sw128(r * 128 + c * 16), A + (long)(row0 + r) * K + k0 + c * 8);
        }
        uint32_t bB = smB + s * B_STG;
        #pragma unroll
        for (int i = 0; i < BN * 8 / 256; i++) {
            int idx = tid + i * 256, r = idx >> 3, c = idx & 7;
            cp16s(bB + sw128(r * 128 + c * 16), Bm + (long)(col0 + r) * K + k0 + c * 8);
        }
        cp_commit();
    };

    const int lane = tid & 31, w = tid >> 5;
    const int g = lane >> 2, tig = lane & 3;
    const int rw = (w % WM) * WTM, cw = (w / WM) * WTN;
    const int aRow = (lane & 7) + ((lane >> 3) & 1) * 8, aChk = lane >> 4;
    const int bRow = (lane & 7) + (lane >> 4) * 8,       bChk = (lane >> 3) & 1;

    float acc[MF][NF][4] = {};

    const int nt = K / BK;                // >= 12 for all our shapes
    load_tile(0, 0);

    for (int it = 0; it < nt; it++) {
        int s = it & 1;
        cp_wait<0>();        // tile it complete (nothing newer outstanding)
        __syncthreads();     // visibility + slot (it-1) fully retired
        if (it + 1 < nt) load_tile((it + 1) * BK, (it + 1) & 1);
        uint32_t aS = smA + s * A_STG, bS = smB + s * B_STG;

        #pragma unroll
        for (int kk = 0; kk < BK; kk += 16) {
            uint32_t afr[MF][4];
            #pragma unroll
            for (int mi = 0; mi < MF; mi++)
                ldsm4(afr[mi], aS + sw128((rw + mi * 16 + aRow) * 128 + ((kk >> 3) + aChk) * 16));
            uint32_t bfr[NF][2];
            #pragma unroll
            for (int j = 0; j < NF / 2; j++) {
                uint32_t r4[4];
                ldsm4(r4, bS + sw128((cw + j * 16 + bRow) * 128 + ((kk >> 3) + bChk) * 16));
                bfr[2*j][0] = r4[0]; bfr[2*j][1] = r4[1];
                bfr[2*j+1][0] = r4[2]; bfr[2*j+1][1] = r4[3];
            }
            #pragma unroll
            for (int mi = 0; mi < MF; mi++)
                #pragma unroll
                for (int ni = 0; ni < NF; ni++)
                    mma16816(acc[mi][ni], afr[mi], bfr[ni]);
        }
        // no bottom barrier
    }

    // ---------------- epilogue ----------------
    #pragma unroll
    for (int mi = 0; mi < MF; mi++) {
        #pragma unroll
        for (int ni = 0; ni < NF; ni++) {
            int r_ = row0 + rw + mi * 16 + g;
            int c_ = col0 + cw + ni * 8 + tig * 2;
            float* a4 = acc[mi][ni];
            #pragma unroll
            for (int half = 0; half < 2; half++) {
                int rr = r_ + half * 8;
                float v0 = a4[half * 2 + 0];
                float v1 = a4[half * 2 + 1];

                if (EPI == EPI_QKV3) {
                    __half* Cp = (__half*)Cv;
                    int seg = c_ / EMB;
                    int cn  = c_ - seg * EMB;
                    int b = rr >> 10, t = rr & 1023;
                    int h = cn >> 6,  d = cn & 63;
                    long o = (long)seg * (NTOK * EMB)
                           + (((long)(b * NH + h) << 10) + t) * HD + d;
                    *(__half2*)&Cp[o] = __floats2half2_rn(v0, v1);
                } else if (EPI == EPI_RES) {
                    float* Cp = (float*)Cv;
                    long o = (long)rr * N + c_;
                    float2 rv = *(const float2*)&R[o];
                    *(float2*)&Cp[o] = make_float2(v0 + rv.x, v1 + rv.y);
                } else if (EPI == EPI_GELU) {
                    __half* Cp = (__half*)Cv;
                    // gelu_tanh(x) = x * sigmoid(2c(x+0.044715x^3)); 2c*log2e folded
                    const float c2 = 2.3022080207180064f;  // 1.59576912... * log2(e)
                    float y0 = c2 * (v0 + 0.044715f * v0 * v0 * v0);
                    float y1 = c2 * (v1 + 0.044715f * v1 * v1 * v1);
                    float g0 = v0 / (1.0f + ex2f(-y0));
                    float g1 = v1 / (1.0f + ex2f(-y1));
                    *(__half2*)&Cp[(long)rr * N + c_] = __floats2half2_rn(g0, g1);
                }
            }
        }
    }
}

// ---------------------------------------------------------------------------
// Launch
// ---------------------------------------------------------------------------
extern "C" void kernel_launch(void* const* d_in, const int* in_sizes, int n_in,
                              void* d_out, int out_size) {
    const float* x    = (const float*)d_in[0];
    const float* wq   = (const float*)d_in[1];
    const float* wk   = (const float*)d_in[2];
    const float* wv   = (const float*)d_in[3];
    const float* wo   = (const float*)d_in[4];
    const float* w1   = (const float*)d_in[5];
    const float* w2   = (const float*)d_in[6];
    const float* ln1s = (const float*)d_in[7];
    const float* ln1b = (const float*)d_in[8];
    const float* ln2s = (const float*)d_in[9];
    const float* ln2b = (const float*)d_in[10];
    float* out = (float*)d_out;

    __half *h16, *qkv16, *ctx16, *ffn16, *wqkv16, *wo16, *w116, *w216;
    float* x2;
    cudaGetSymbolAddress((void**)&h16,    g_h16);
    cudaGetSymbolAddress((void**)&qkv16,  g_qkv16);
    cudaGetSymbolAddress((void**)&ctx16,  g_ctx16);
    cudaGetSymbolAddress((void**)&ffn16,  g_ffn16);
    cudaGetSymbolAddress((void**)&x2,     g_x2);
    cudaGetSymbolAddress((void**)&wqkv16, g_wqkv16);
    cudaGetSymbolAddress((void**)&wo16,   g_wo16);
    cudaGetSymbolAddress((void**)&w116,   g_w116);
    cudaGetSymbolAddress((void**)&w216,   g_w216);

    __half* q16 = qkv16;
    __half* k16 = qkv16 + (long)NTOK * EMB;
    __half* v16 = qkv16 + 2L * NTOK * EMB;

    constexpr int SM_NT    = 2 * (128 * 64 + 128 * 64) * 2;    // 65536 B -> 2 CTAs/SM
    constexpr int SM_FLASH = 128 * 128 + 2 * 3 * 64 * 128 * 2; // 65536 B

    cudaFuncSetAttribute(gemm_h<128,128,2,4,EPI_QKV3>,
                         cudaFuncAttributeMaxDynamicSharedMemorySize, SM_NT);
    cudaFuncSetAttribute(gemm_h<128,128,2,4,EPI_RES>,
                         cudaFuncAttributeMaxDynamicSharedMemorySize, SM_NT);
    cudaFuncSetAttribute(gemm_h<128,128,2,4,EPI_GELU>,
                         cudaFuncAttributeMaxDynamicSharedMemorySize, SM_NT);
    cudaFuncSetAttribute(flash_k,
                         cudaFuncAttributeMaxDynamicSharedMemorySize, SM_FLASH);

    // 0) all weight fp32 -> fp16 conversions in one launch
    f2h_all_k<<<dim3(FFND * EMB / 1024, 6), 256>>>(
        wq, wk, wv, wo, w1, w2, wqkv16, wo16, w116, w216);

    // 1) LN1 (fp32 -> fp16), warp-per-row
    layernorm_k<<<NTOK / 8, 256>>>(x, h16, ln1s, ln1b);

    // 2) fused QKV projection : M=8192, N=2304, K=768 -> q|k|v [B,H,T,D]
    gemm_h<128,128,2,4,EPI_QKV3><<<dim3(3 * EMB / 128, NTOK / 128), 256, SM_NT>>>(
        h16, wqkv16, nullptr, qkv16, NTOK, 3 * EMB, EMB);

    // 3) flash attention -> ctx fp16 [B,T,E]
    flash_k<<<dim3(Tseq / 128, Bsz * NH), 256, SM_FLASH>>>(q16, k16, v16, ctx16);

    // 4) x2 = x + ctx @ Wo^T (fp32 residual) : M=8192, N=768, K=768
    gemm_h<128,128,2,4,EPI_RES><<<dim3(EMB / 128, NTOK / 128), 256, SM_NT>>>(
        ctx16, wo16, x, x2, NTOK, EMB, EMB);

    // 5) LN2 (fp32 -> fp16), warp-per-row
    layernorm_k<<<NTOK / 8, 256>>>(x2, h16, ln2s, ln2b);

    // 6) ffn = gelu(h @ W1^T) fp16 : M=8192, N=3072, K=768
    gemm_h<128,128,2,4,EPI_GELU><<<dim3(FFND / 128, NTOK / 128), 256, SM_NT>>>(
        h16, w116, nullptr, ffn16, NTOK, FFND, EMB);

    // 7) out = x2 + ffn @ W2^T (fp32 residual) : M=8192, N=768, K=3072
    gemm_h<128,128,2,4,EPI_RES><<<dim3(EMB / 128, NTOK / 128), 256, SM_NT>>>(
        ffn16, w216, x2, out, NTOK, EMB, FFND);
}